// round 1
// baseline (speedup 1.0000x reference)
#include <cuda_runtime.h>
#include <cuda_bf16.h>
#include <math.h>

// Problem constants
#define BATCH   2
#define SEQ     2048
#define DMODEL  512
#define NHEADS  8
#define DHEAD   64
#define MTOT    (BATCH * SEQ)          // 4096 rows for projection GEMMs

// ---------------- scratch (static device arrays; no allocation) -------------
__device__ float g_qp [BATCH * SEQ * DMODEL];
__device__ float g_kp [BATCH * SEQ * DMODEL];
__device__ float g_vp [BATCH * SEQ * DMODEL];
__device__ float g_att[BATCH * SEQ * DMODEL];

// ---------------- tiled SGEMM: out[m][n] = sum_k A[m][k]*W[n][k] + bias[n] --
// 64x64 output tile per block, 256 threads, 4x4 per thread, BK=16.
__global__ __launch_bounds__(256)
void gemm_bias_kernel(const float* __restrict__ A,
                      const float* __restrict__ W,
                      const float* __restrict__ bias,
                      float* __restrict__ out,
                      int M, int N, int K)
{
    __shared__ float As[64][17];
    __shared__ float Bs[64][17];

    const int tid = threadIdx.x;
    const int tx  = tid & 15;       // 0..15  -> n sub-tile
    const int ty  = tid >> 4;       // 0..15  -> m sub-tile
    const int m0  = blockIdx.y * 64;
    const int n0  = blockIdx.x * 64;

    const int lr = tid >> 2;            // 0..63 load row
    const int lc = (tid & 3) << 2;      // 0,4,8,12 load col (float4)

    const float* Aptr = A + (size_t)(m0 + lr) * K + lc;
    const float* Wptr = W + (size_t)(n0 + lr) * K + lc;

    float acc[4][4];
#pragma unroll
    for (int i = 0; i < 4; i++)
#pragma unroll
        for (int j = 0; j < 4; j++) acc[i][j] = 0.f;

    for (int kt = 0; kt < K; kt += 16) {
        float4 a4 = *(const float4*)(Aptr + kt);
        float4 b4 = *(const float4*)(Wptr + kt);
        As[lr][lc + 0] = a4.x; As[lr][lc + 1] = a4.y;
        As[lr][lc + 2] = a4.z; As[lr][lc + 3] = a4.w;
        Bs[lr][lc + 0] = b4.x; Bs[lr][lc + 1] = b4.y;
        Bs[lr][lc + 2] = b4.z; Bs[lr][lc + 3] = b4.w;
        __syncthreads();

#pragma unroll
        for (int k = 0; k < 16; k++) {
            float a[4], b[4];
#pragma unroll
            for (int i = 0; i < 4; i++) a[i] = As[ty * 4 + i][k];
#pragma unroll
            for (int j = 0; j < 4; j++) b[j] = Bs[tx * 4 + j][k];
#pragma unroll
            for (int i = 0; i < 4; i++)
#pragma unroll
                for (int j = 0; j < 4; j++)
                    acc[i][j] = fmaf(a[i], b[j], acc[i][j]);
        }
        __syncthreads();
    }

#pragma unroll
    for (int i = 0; i < 4; i++) {
        const int m = m0 + ty * 4 + i;
#pragma unroll
        for (int j = 0; j < 4; j++) {
            const int n = n0 + tx * 4 + j;
            out[(size_t)m * N + n] = acc[i][j] + bias[n];
        }
    }
}

// ---------------- flash attention (fp32, online softmax) --------------------
// One block handles 64 query rows of one (b, h). Streams KV in 64-row tiles.
// 256 threads (16x16); each thread owns a 4x4 sub-tile of S and of O.
#define FPAD 65
__global__ __launch_bounds__(256)
void flash_attn_kernel(const float* __restrict__ qp,
                       const float* __restrict__ kp,
                       const float* __restrict__ vp,
                       float* __restrict__ att)
{
    extern __shared__ float sm[];
    float* Qs = sm;                    // 64*65
    float* Ks = Qs + 64 * FPAD;
    float* Vs = Ks + 64 * FPAD;
    float* Ps = Vs + 64 * FPAD;

    const int tid = threadIdx.x;
    const int tx  = tid & 15;
    const int ty  = tid >> 4;

    const int s0 = blockIdx.x * 64;    // query tile start
    const int h  = blockIdx.y;
    const int b  = blockIdx.z;

    // base offset of element [b, s=0, h*DHEAD] in a [B,S,DMODEL] tensor
    const size_t base = (size_t)b * SEQ * DMODEL + (size_t)h * DHEAD;

    // ---- load Q tile (64 x 64) ----
    {
        const int r  = tid >> 2;            // 0..63
        const int c0 = (tid & 3) << 4;      // 0,16,32,48 : 16 floats per thread
        const float* src = qp + base + (size_t)(s0 + r) * DMODEL + c0;
#pragma unroll
        for (int i = 0; i < 4; i++) {
            float4 v4 = *(const float4*)(src + i * 4);
            Qs[r * FPAD + c0 + i * 4 + 0] = v4.x;
            Qs[r * FPAD + c0 + i * 4 + 1] = v4.y;
            Qs[r * FPAD + c0 + i * 4 + 2] = v4.z;
            Qs[r * FPAD + c0 + i * 4 + 3] = v4.w;
        }
    }

    float m_run[4], l_run[4], Oacc[4][4];
#pragma unroll
    for (int i = 0; i < 4; i++) {
        m_run[i] = -INFINITY;
        l_run[i] = 0.f;
#pragma unroll
        for (int j = 0; j < 4; j++) Oacc[i][j] = 0.f;
    }

    const float scale = 0.125f;  // 1/sqrt(64)

    for (int kt = 0; kt < SEQ; kt += 64) {
        __syncthreads();  // previous iteration done reading Ks/Vs/Ps

        // ---- load K,V tiles (64 x 64 each) ----
        {
            const int r  = tid >> 2;
            const int c0 = (tid & 3) << 4;
            const float* ksrc = kp + base + (size_t)(kt + r) * DMODEL + c0;
            const float* vsrc = vp + base + (size_t)(kt + r) * DMODEL + c0;
#pragma unroll
            for (int i = 0; i < 4; i++) {
                float4 k4 = *(const float4*)(ksrc + i * 4);
                Ks[r * FPAD + c0 + i * 4 + 0] = k4.x;
                Ks[r * FPAD + c0 + i * 4 + 1] = k4.y;
                Ks[r * FPAD + c0 + i * 4 + 2] = k4.z;
                Ks[r * FPAD + c0 + i * 4 + 3] = k4.w;
                float4 v4 = *(const float4*)(vsrc + i * 4);
                Vs[r * FPAD + c0 + i * 4 + 0] = v4.x;
                Vs[r * FPAD + c0 + i * 4 + 1] = v4.y;
                Vs[r * FPAD + c0 + i * 4 + 2] = v4.z;
                Vs[r * FPAD + c0 + i * 4 + 3] = v4.w;
            }
        }
        __syncthreads();

        // ---- S = Q K^T (4x4 per thread) ----
        float s[4][4];
#pragma unroll
        for (int i = 0; i < 4; i++)
#pragma unroll
            for (int j = 0; j < 4; j++) s[i][j] = 0.f;

#pragma unroll 8
        for (int d = 0; d < DHEAD; d++) {
            float a[4], bq[4];
#pragma unroll
            for (int i = 0; i < 4; i++) a[i]  = Qs[(ty * 4 + i) * FPAD + d];
#pragma unroll
            for (int j = 0; j < 4; j++) bq[j] = Ks[(tx * 4 + j) * FPAD + d];
#pragma unroll
            for (int i = 0; i < 4; i++)
#pragma unroll
                for (int j = 0; j < 4; j++)
                    s[i][j] = fmaf(a[i], bq[j], s[i][j]);
        }

        // ---- online softmax update ----
        float tmax[4], psum[4];
#pragma unroll
        for (int i = 0; i < 4; i++) {
#pragma unroll
            for (int j = 0; j < 4; j++) s[i][j] *= scale;
            float mx = s[i][0];
            mx = fmaxf(mx, s[i][1]); mx = fmaxf(mx, s[i][2]); mx = fmaxf(mx, s[i][3]);
            tmax[i] = mx;
        }
#pragma unroll
        for (int off = 8; off >= 1; off >>= 1)
#pragma unroll
            for (int i = 0; i < 4; i++)
                tmax[i] = fmaxf(tmax[i], __shfl_xor_sync(0xffffffffu, tmax[i], off, 16));

#pragma unroll
        for (int i = 0; i < 4; i++) {
            const float mnew  = fmaxf(m_run[i], tmax[i]);
            const float alpha = __expf(m_run[i] - mnew);   // 0 on first tile
            float ps = 0.f;
#pragma unroll
            for (int j = 0; j < 4; j++) {
                s[i][j] = __expf(s[i][j] - mnew);
                ps += s[i][j];
            }
            psum[i]  = ps;
            m_run[i] = mnew;
            l_run[i] = l_run[i] * alpha;
#pragma unroll
            for (int j = 0; j < 4; j++) Oacc[i][j] *= alpha;
        }
#pragma unroll
        for (int off = 8; off >= 1; off >>= 1)
#pragma unroll
            for (int i = 0; i < 4; i++)
                psum[i] += __shfl_xor_sync(0xffffffffu, psum[i], off, 16);
#pragma unroll
        for (int i = 0; i < 4; i++) l_run[i] += psum[i];

        // ---- stage P to smem ----
#pragma unroll
        for (int i = 0; i < 4; i++)
#pragma unroll
            for (int j = 0; j < 4; j++)
                Ps[(ty * 4 + i) * FPAD + tx * 4 + j] = s[i][j];
        __syncthreads();

        // ---- O += P @ V (thread owns rows ty*4.., d-cols tx*4..) ----
#pragma unroll 8
        for (int c = 0; c < 64; c++) {
            float a[4], vv[4];
#pragma unroll
            for (int i = 0; i < 4; i++) a[i]  = Ps[(ty * 4 + i) * FPAD + c];
#pragma unroll
            for (int j = 0; j < 4; j++) vv[j] = Vs[c * FPAD + tx * 4 + j];
#pragma unroll
            for (int i = 0; i < 4; i++)
#pragma unroll
                for (int j = 0; j < 4; j++)
                    Oacc[i][j] = fmaf(a[i], vv[j], Oacc[i][j]);
        }
    }

    // ---- epilogue: normalize and write [b, s, h*64 + d] ----
#pragma unroll
    for (int i = 0; i < 4; i++) {
        const float inv_l = 1.0f / l_run[i];
        const int   srow  = s0 + ty * 4 + i;
#pragma unroll
        for (int j = 0; j < 4; j++) {
            att[base + (size_t)srow * DMODEL + tx * 4 + j] = Oacc[i][j] * inv_l;
        }
    }
}

// ---------------- host launcher ---------------------------------------------
extern "C" void kernel_launch(void* const* d_in, const int* in_sizes, int n_in,
                              void* d_out, int out_size)
{
    const float* q    = (const float*)d_in[0];
    const float* k    = (const float*)d_in[1];
    const float* v    = (const float*)d_in[2];
    const float* Wq_w = (const float*)d_in[3];
    const float* Wq_b = (const float*)d_in[4];
    const float* Wc_w = (const float*)d_in[5];
    const float* Wc_b = (const float*)d_in[6];
    float* out = (float*)d_out;

    float *qp, *kp, *vp, *attp;
    cudaGetSymbolAddress((void**)&qp,   g_qp);
    cudaGetSymbolAddress((void**)&kp,   g_kp);
    cudaGetSymbolAddress((void**)&vp,   g_vp);
    cudaGetSymbolAddress((void**)&attp, g_att);

    // projections: [4096,512] = X @ Wq^T + b   (q, k, v all use Wq per reference)
    dim3 gblk(DMODEL / 64, MTOT / 64);   // (8, 64)
    gemm_bias_kernel<<<gblk, 256>>>(q, Wq_w, Wq_b, qp, MTOT, DMODEL, DMODEL);
    gemm_bias_kernel<<<gblk, 256>>>(k, Wq_w, Wq_b, kp, MTOT, DMODEL, DMODEL);
    gemm_bias_kernel<<<gblk, 256>>>(v, Wq_w, Wq_b, vp, MTOT, DMODEL, DMODEL);

    // flash attention
    const int smem = 4 * 64 * FPAD * (int)sizeof(float);   // 66560 B
    cudaFuncSetAttribute(flash_attn_kernel,
                         cudaFuncAttributeMaxDynamicSharedMemorySize, smem);
    dim3 fgrid(SEQ / 64, NHEADS, BATCH); // (32, 8, 2)
    flash_attn_kernel<<<fgrid, 256, smem>>>(qp, kp, vp, attp);

    // output projection: [4096,512] = att @ Wc^T + b
    gemm_bias_kernel<<<gblk, 256>>>(attp, Wc_w, Wc_b, out, MTOT, DMODEL, DMODEL);
}

// round 2
// speedup vs baseline: 1.4282x; 1.4282x over previous
#include <cuda_runtime.h>
#include <cuda_bf16.h>
#include <math.h>

// Problem constants
#define BATCH   2
#define SEQ     2048
#define DMODEL  512
#define NHEADS  8
#define DHEAD   64
#define MTOT    (BATCH * SEQ)          // 4096 rows for projection GEMMs

// ---------------- scratch (static device arrays; no allocation) -------------
__device__ float g_qp [BATCH * SEQ * DMODEL];
__device__ float g_kp [BATCH * SEQ * DMODEL];
__device__ float g_vp [BATCH * SEQ * DMODEL];
__device__ float g_att[BATCH * SEQ * DMODEL];

// ============================================================================
// Tiled SGEMM: out[m][n] = sum_k A[m][k]*W[n][k] + bias[n]
// Tile 128m x 64n, BK=16, 256 threads, 8x4 microtile.
// A and W staged TRANSPOSED in smem ([k][m] / [k][n]) so the inner loop is
// pure LDS.128: 3 vector loads + 32 FMA per k-step.
// ============================================================================
#define G_MP 132   // padded m stride (floats) for As
#define G_NP 68    // padded n stride for Ws

__global__ __launch_bounds__(256)
void gemm_bias_kernel(const float* __restrict__ A,
                      const float* __restrict__ W,
                      const float* __restrict__ bias,
                      float* __restrict__ out,
                      int M, int N, int K)
{
    __shared__ float As[16 * G_MP];   // As[k][m]
    __shared__ float Ws[16 * G_NP];   // Ws[k][n]

    const int tid = threadIdx.x;
    const int tx  = tid & 15;        // n group: cols tx*4 .. +3
    const int ty  = tid >> 4;        // m group: rows ty*8 .. +7
    const int m0  = blockIdx.y * 128;
    const int n0  = blockIdx.x * 64;

    // A loader mapping: 128 rows x 16 k per tile, 2 float4 per thread
    const int a_m  = tid >> 1;              // 0..127
    const int a_k0 = (tid & 1) * 8;         // 0 or 8
    // W loader mapping: 64 rows x 16 k, 1 float4 per thread
    const int w_n  = tid >> 2;              // 0..63
    const int w_k0 = (tid & 3) * 4;         // 0,4,8,12

    const float* Aptr = A + (size_t)(m0 + a_m) * K + a_k0;
    const float* Wptr = W + (size_t)(n0 + w_n) * K + w_k0;

    float acc[8][4];
#pragma unroll
    for (int i = 0; i < 8; i++)
#pragma unroll
        for (int j = 0; j < 4; j++) acc[i][j] = 0.f;

    for (int kt = 0; kt < K; kt += 16) {
        float4 a4a = *(const float4*)(Aptr + kt);
        float4 a4b = *(const float4*)(Aptr + kt + 4);
        float4 w4  = *(const float4*)(Wptr + kt);
        __syncthreads();
        // transposed scalar stores
        As[(a_k0 + 0) * G_MP + a_m] = a4a.x;
        As[(a_k0 + 1) * G_MP + a_m] = a4a.y;
        As[(a_k0 + 2) * G_MP + a_m] = a4a.z;
        As[(a_k0 + 3) * G_MP + a_m] = a4a.w;
        As[(a_k0 + 4) * G_MP + a_m] = a4b.x;
        As[(a_k0 + 5) * G_MP + a_m] = a4b.y;
        As[(a_k0 + 6) * G_MP + a_m] = a4b.z;
        As[(a_k0 + 7) * G_MP + a_m] = a4b.w;
        Ws[(w_k0 + 0) * G_NP + w_n] = w4.x;
        Ws[(w_k0 + 1) * G_NP + w_n] = w4.y;
        Ws[(w_k0 + 2) * G_NP + w_n] = w4.z;
        Ws[(w_k0 + 3) * G_NP + w_n] = w4.w;
        __syncthreads();

#pragma unroll
        for (int k = 0; k < 16; k++) {
            float4 a0 = *(const float4*)(&As[k * G_MP + ty * 8]);
            float4 a1 = *(const float4*)(&As[k * G_MP + ty * 8 + 4]);
            float4 b  = *(const float4*)(&Ws[k * G_NP + tx * 4]);
            float av[8] = {a0.x, a0.y, a0.z, a0.w, a1.x, a1.y, a1.z, a1.w};
            float bv[4] = {b.x, b.y, b.z, b.w};
#pragma unroll
            for (int i = 0; i < 8; i++)
#pragma unroll
                for (int j = 0; j < 4; j++)
                    acc[i][j] = fmaf(av[i], bv[j], acc[i][j]);
        }
    }

    float4 bb = *(const float4*)(bias + n0 + tx * 4);
#pragma unroll
    for (int i = 0; i < 8; i++) {
        const int m = m0 + ty * 8 + i;
        float4 o;
        o.x = acc[i][0] + bb.x;
        o.y = acc[i][1] + bb.y;
        o.z = acc[i][2] + bb.z;
        o.w = acc[i][3] + bb.w;
        *(float4*)(out + (size_t)m * N + n0 + tx * 4) = o;
    }
}

// Batched variant for the three input projections (all use Wq).
__global__ __launch_bounds__(256)
void proj3_kernel(const float* __restrict__ q,
                  const float* __restrict__ k,
                  const float* __restrict__ v,
                  const float* __restrict__ W,
                  const float* __restrict__ bias,
                  float* __restrict__ qp,
                  float* __restrict__ kp,
                  float* __restrict__ vp)
{
    __shared__ float As[16 * G_MP];
    __shared__ float Ws[16 * G_NP];

    const float* A;
    float* out;
    if (blockIdx.z == 0)      { A = q; out = qp; }
    else if (blockIdx.z == 1) { A = k; out = kp; }
    else                      { A = v; out = vp; }

    const int K = DMODEL, N = DMODEL;
    const int tid = threadIdx.x;
    const int tx  = tid & 15;
    const int ty  = tid >> 4;
    const int m0  = blockIdx.y * 128;
    const int n0  = blockIdx.x * 64;

    const int a_m  = tid >> 1;
    const int a_k0 = (tid & 1) * 8;
    const int w_n  = tid >> 2;
    const int w_k0 = (tid & 3) * 4;

    const float* Aptr = A + (size_t)(m0 + a_m) * K + a_k0;
    const float* Wptr = W + (size_t)(n0 + w_n) * K + w_k0;

    float acc[8][4];
#pragma unroll
    for (int i = 0; i < 8; i++)
#pragma unroll
        for (int j = 0; j < 4; j++) acc[i][j] = 0.f;

    for (int kt = 0; kt < K; kt += 16) {
        float4 a4a = *(const float4*)(Aptr + kt);
        float4 a4b = *(const float4*)(Aptr + kt + 4);
        float4 w4  = *(const float4*)(Wptr + kt);
        __syncthreads();
        As[(a_k0 + 0) * G_MP + a_m] = a4a.x;
        As[(a_k0 + 1) * G_MP + a_m] = a4a.y;
        As[(a_k0 + 2) * G_MP + a_m] = a4a.z;
        As[(a_k0 + 3) * G_MP + a_m] = a4a.w;
        As[(a_k0 + 4) * G_MP + a_m] = a4b.x;
        As[(a_k0 + 5) * G_MP + a_m] = a4b.y;
        As[(a_k0 + 6) * G_MP + a_m] = a4b.z;
        As[(a_k0 + 7) * G_MP + a_m] = a4b.w;
        Ws[(w_k0 + 0) * G_NP + w_n] = w4.x;
        Ws[(w_k0 + 1) * G_NP + w_n] = w4.y;
        Ws[(w_k0 + 2) * G_NP + w_n] = w4.z;
        Ws[(w_k0 + 3) * G_NP + w_n] = w4.w;
        __syncthreads();

#pragma unroll
        for (int k = 0; k < 16; k++) {
            float4 a0 = *(const float4*)(&As[k * G_MP + ty * 8]);
            float4 a1 = *(const float4*)(&As[k * G_MP + ty * 8 + 4]);
            float4 b  = *(const float4*)(&Ws[k * G_NP + tx * 4]);
            float av[8] = {a0.x, a0.y, a0.z, a0.w, a1.x, a1.y, a1.z, a1.w};
            float bv[4] = {b.x, b.y, b.z, b.w};
#pragma unroll
            for (int i = 0; i < 8; i++)
#pragma unroll
                for (int j = 0; j < 4; j++)
                    acc[i][j] = fmaf(av[i], bv[j], acc[i][j]);
        }
    }

    float4 bb = *(const float4*)(bias + n0 + tx * 4);
#pragma unroll
    for (int i = 0; i < 8; i++) {
        const int m = m0 + ty * 8 + i;
        float4 o;
        o.x = acc[i][0] + bb.x;
        o.y = acc[i][1] + bb.y;
        o.z = acc[i][2] + bb.z;
        o.w = acc[i][3] + bb.w;
        *(float4*)(out + (size_t)m * N + n0 + tx * 4) = o;
    }
}

// ============================================================================
// Flash attention (fp32, online softmax), 128 q-rows x 64 kv-cols tiles.
// 256 threads, 8x4 microtile. All hot-loop smem reads are float4 or broadcast.
//   Qs[d][m]  (64 x 132)  transposed
//   Ks[d][n]  (64 x 68)   transposed
//   Vs[c][dv] (64 x 68)   natural
//   Ps[m][c]  (128 x 68)  natural (vector stores, broadcast reads)
// ============================================================================
#define F_MP 132
#define F_NP 68

__global__ __launch_bounds__(256, 2)
void flash_attn_kernel(const float* __restrict__ qp,
                       const float* __restrict__ kp,
                       const float* __restrict__ vp,
                       float* __restrict__ att)
{
    extern __shared__ float sm[];
    float* Qs = sm;                        // 64*132 = 8448
    float* Ks = Qs + 64 * F_MP;            // 64*68  = 4352
    float* Vs = Ks + 64 * F_NP;            // 64*68  = 4352
    float* Ps = Vs + 64 * F_NP;            // 128*68 = 8704

    const int tid = threadIdx.x;
    const int tx  = tid & 15;              // kv cols tx*4..+3
    const int ty  = tid >> 4;              // q rows ty*8..+7

    const int s0 = blockIdx.x * 128;       // query tile start
    const int h  = blockIdx.y;
    const int b  = blockIdx.z;

    const size_t base = (size_t)b * SEQ * DMODEL + (size_t)h * DHEAD;

    // ---- load Q tile (128 x 64) transposed into Qs[d][m] ----
    {
        const int r  = tid >> 1;            // 0..127
        const int c0 = (tid & 1) * 32;      // 0 or 32
        const float* src = qp + base + (size_t)(s0 + r) * DMODEL + c0;
#pragma unroll
        for (int i = 0; i < 8; i++) {
            float4 v4 = *(const float4*)(src + i * 4);
            const int d = c0 + i * 4;
            Qs[(d + 0) * F_MP + r] = v4.x;
            Qs[(d + 1) * F_MP + r] = v4.y;
            Qs[(d + 2) * F_MP + r] = v4.z;
            Qs[(d + 3) * F_MP + r] = v4.w;
        }
    }

    float m_run[8], l_run[8], Oacc[8][4];
#pragma unroll
    for (int i = 0; i < 8; i++) {
        m_run[i] = -INFINITY;
        l_run[i] = 0.f;
#pragma unroll
        for (int j = 0; j < 4; j++) Oacc[i][j] = 0.f;
    }

    const float scale = 0.125f;  // 1/sqrt(64)

    for (int kt = 0; kt < SEQ; kt += 64) {
        __syncthreads();  // previous iteration done reading Ks/Vs/Ps

        // ---- load K (transposed) and V (natural) tiles ----
        {
            const int r  = tid >> 2;            // 0..63
            const int c0 = (tid & 3) * 16;      // 0,16,32,48
            const float* ksrc = kp + base + (size_t)(kt + r) * DMODEL + c0;
            const float* vsrc = vp + base + (size_t)(kt + r) * DMODEL + c0;
#pragma unroll
            for (int i = 0; i < 4; i++) {
                float4 k4 = *(const float4*)(ksrc + i * 4);
                const int d = c0 + i * 4;
                Ks[(d + 0) * F_NP + r] = k4.x;
                Ks[(d + 1) * F_NP + r] = k4.y;
                Ks[(d + 2) * F_NP + r] = k4.z;
                Ks[(d + 3) * F_NP + r] = k4.w;
                float4 v4 = *(const float4*)(vsrc + i * 4);
                *(float4*)(&Vs[r * F_NP + c0 + i * 4]) = v4;
            }
        }
        __syncthreads();

        // ---- S = Q K^T : per d, 3x LDS.128 + 32 FMA ----
        float s[8][4];
#pragma unroll
        for (int i = 0; i < 8; i++)
#pragma unroll
            for (int j = 0; j < 4; j++) s[i][j] = 0.f;

#pragma unroll 4
        for (int d = 0; d < DHEAD; d++) {
            float4 a0 = *(const float4*)(&Qs[d * F_MP + ty * 8]);
            float4 a1 = *(const float4*)(&Qs[d * F_MP + ty * 8 + 4]);
            float4 bq = *(const float4*)(&Ks[d * F_NP + tx * 4]);
            float av[8] = {a0.x, a0.y, a0.z, a0.w, a1.x, a1.y, a1.z, a1.w};
            float bv[4] = {bq.x, bq.y, bq.z, bq.w};
#pragma unroll
            for (int i = 0; i < 8; i++)
#pragma unroll
                for (int j = 0; j < 4; j++)
                    s[i][j] = fmaf(av[i], bv[j], s[i][j]);
        }

        // ---- online softmax update (rows i, reduce across tx: 16 lanes) ----
        float tmax[8];
#pragma unroll
        for (int i = 0; i < 8; i++) {
#pragma unroll
            for (int j = 0; j < 4; j++) s[i][j] *= scale;
            float mx = fmaxf(fmaxf(s[i][0], s[i][1]), fmaxf(s[i][2], s[i][3]));
            tmax[i] = mx;
        }
#pragma unroll
        for (int off = 8; off >= 1; off >>= 1)
#pragma unroll
            for (int i = 0; i < 8; i++)
                tmax[i] = fmaxf(tmax[i], __shfl_xor_sync(0xffffffffu, tmax[i], off, 16));

        float psum[8];
#pragma unroll
        for (int i = 0; i < 8; i++) {
            const float mnew  = fmaxf(m_run[i], tmax[i]);
            const float alpha = __expf(m_run[i] - mnew);   // 0 on first tile
            float ps = 0.f;
#pragma unroll
            for (int j = 0; j < 4; j++) {
                s[i][j] = __expf(s[i][j] - mnew);
                ps += s[i][j];
            }
            psum[i]  = ps;
            m_run[i] = mnew;
            l_run[i] = l_run[i] * alpha;
#pragma unroll
            for (int j = 0; j < 4; j++) Oacc[i][j] *= alpha;
        }
#pragma unroll
        for (int off = 8; off >= 1; off >>= 1)
#pragma unroll
            for (int i = 0; i < 8; i++)
                psum[i] += __shfl_xor_sync(0xffffffffu, psum[i], off, 16);
#pragma unroll
        for (int i = 0; i < 8; i++) l_run[i] += psum[i];

        // ---- stage P to smem: vector store of owned 4 contiguous cols ----
#pragma unroll
        for (int i = 0; i < 8; i++) {
            float4 p4 = make_float4(s[i][0], s[i][1], s[i][2], s[i][3]);
            *(float4*)(&Ps[(ty * 8 + i) * F_NP + tx * 4]) = p4;
        }
        __syncthreads();

        // ---- O += P @ V : per c, 8 broadcast LDS + 1 LDS.128 + 32 FMA ----
#pragma unroll 4
        for (int c = 0; c < 64; c++) {
            float4 vv = *(const float4*)(&Vs[c * F_NP + tx * 4]);
            float bv[4] = {vv.x, vv.y, vv.z, vv.w};
            float av[8];
#pragma unroll
            for (int i = 0; i < 8; i++) av[i] = Ps[(ty * 8 + i) * F_NP + c];
#pragma unroll
            for (int i = 0; i < 8; i++)
#pragma unroll
                for (int j = 0; j < 4; j++)
                    Oacc[i][j] = fmaf(av[i], bv[j], Oacc[i][j]);
        }
    }

    // ---- epilogue: normalize and write [b, s, h*64 + d] (float4) ----
#pragma unroll
    for (int i = 0; i < 8; i++) {
        const float inv_l = 1.0f / l_run[i];
        const int   srow  = s0 + ty * 8 + i;
        float4 o;
        o.x = Oacc[i][0] * inv_l;
        o.y = Oacc[i][1] * inv_l;
        o.z = Oacc[i][2] * inv_l;
        o.w = Oacc[i][3] * inv_l;
        *(float4*)(att + base + (size_t)srow * DMODEL + tx * 4) = o;
    }
}

// ---------------- host launcher ---------------------------------------------
extern "C" void kernel_launch(void* const* d_in, const int* in_sizes, int n_in,
                              void* d_out, int out_size)
{
    const float* q    = (const float*)d_in[0];
    const float* k    = (const float*)d_in[1];
    const float* v    = (const float*)d_in[2];
    const float* Wq_w = (const float*)d_in[3];
    const float* Wq_b = (const float*)d_in[4];
    const float* Wc_w = (const float*)d_in[5];
    const float* Wc_b = (const float*)d_in[6];
    float* out = (float*)d_out;

    float *qp, *kp, *vp, *attp;
    cudaGetSymbolAddress((void**)&qp,   g_qp);
    cudaGetSymbolAddress((void**)&kp,   g_kp);
    cudaGetSymbolAddress((void**)&vp,   g_vp);
    cudaGetSymbolAddress((void**)&attp, g_att);

    // three input projections in one batched launch (all use Wq)
    dim3 pgrid(DMODEL / 64, MTOT / 128, 3);   // (8, 32, 3)
    proj3_kernel<<<pgrid, 256>>>(q, k, v, Wq_w, Wq_b, qp, kp, vp);

    // flash attention
    const int smem = (64 * F_MP + 64 * F_NP + 64 * F_NP + 128 * F_NP) * (int)sizeof(float);
    cudaFuncSetAttribute(flash_attn_kernel,
                         cudaFuncAttributeMaxDynamicSharedMemorySize, smem);
    dim3 fgrid(SEQ / 128, NHEADS, BATCH);     // (16, 8, 2)
    flash_attn_kernel<<<fgrid, 256, smem>>>(qp, kp, vp, attp);

    // output projection
    dim3 ogrid(DMODEL / 64, MTOT / 128);      // (8, 32)
    gemm_bias_kernel<<<ogrid, 256>>>(attp, Wc_w, Wc_b, out, MTOT, DMODEL, DMODEL);
}

// round 3
// speedup vs baseline: 3.2632x; 2.2849x over previous
#include <cuda_runtime.h>
#include <cuda_bf16.h>
#include <math.h>

// Problem constants
#define BATCH   2
#define SEQ     2048
#define DMODEL  512
#define NHEADS  8
#define DHEAD   64
#define MTOT    (BATCH * SEQ)

// ---------------- scratch (static device arrays; no allocation) -------------
__device__ float g_qp [BATCH * SEQ * DMODEL];
__device__ float g_kp [BATCH * SEQ * DMODEL];
__device__ float g_vp [BATCH * SEQ * DMODEL];
__device__ float g_att[BATCH * SEQ * DMODEL];

// ---------------- tf32 mma helpers ------------------------------------------
__device__ __forceinline__ unsigned f2tf32(float x) {
    unsigned u;
    asm("cvt.rna.tf32.f32 %0, %1;" : "=r"(u) : "f"(x));
    return u;
}

__device__ __forceinline__ void mma_tf32(float c[4],
                                         unsigned a0, unsigned a1,
                                         unsigned a2, unsigned a3,
                                         unsigned b0, unsigned b1) {
    asm volatile(
        "mma.sync.aligned.m16n8k8.row.col.f32.tf32.tf32.f32 "
        "{%0,%1,%2,%3}, {%4,%5,%6,%7}, {%8,%9}, {%0,%1,%2,%3};"
        : "+f"(c[0]), "+f"(c[1]), "+f"(c[2]), "+f"(c[3])
        : "r"(a0), "r"(a1), "r"(a2), "r"(a3), "r"(b0), "r"(b1));
}

// pair-permutation: (k, k+4) become adjacent -> one LDS.64 per fragment pair
#define P8(k) (((k) & ~7) | (((k) & 3) << 1) | (((k) >> 2) & 1))

// ============================================================================
// tf32 GEMM: out[m][n] = sum_k A[m][k] * W[n][k] + bias[n]
// Block tile 128m x 128n, BK=32, 256 threads = 8 warps (2m x 4n),
// warp tile 64m x 32n (4 x 4 m16n8k8 per k-chunk).
// ============================================================================
#define APAD 40   // 40 % 32 == 8 -> conflict-free LDS.64 fragment loads

__device__ __forceinline__ void gemm_mma_body(const float* __restrict__ A,
                                              const float* __restrict__ W,
                                              const float* __restrict__ bias,
                                              float* __restrict__ out,
                                              int m0, int n0)
{
    __shared__ unsigned As[128 * APAD];
    __shared__ unsigned Ws[128 * APAD];

    const int tid  = threadIdx.x;
    const int warp = tid >> 5;
    const int lane = tid & 31;
    const int g    = lane >> 2;       // group id (row within m16/n8)
    const int th   = lane & 3;        // thread in group (k / col pair)
    const int wm   = warp >> 2;       // 0..1
    const int wn   = warp & 3;        // 0..3

    float acc[4][4][4];
#pragma unroll
    for (int mt = 0; mt < 4; mt++)
#pragma unroll
        for (int nt = 0; nt < 4; nt++)
#pragma unroll
            for (int i = 0; i < 4; i++) acc[mt][nt][i] = 0.f;

    for (int kt = 0; kt < DMODEL; kt += 32) {
        __syncthreads();
        // stage A and W tiles (128 x 32 each), tf32-converted, p8-permuted
#pragma unroll
        for (int i = 0; i < 4; i++) {
            const int idx = i * 256 + tid;       // 0..1023 float4 slots
            const int row = idx >> 3;            // 0..127
            const int kq  = (idx & 7) << 2;      // 0,4,...,28
            float4 a4 = *(const float4*)(A + (size_t)(m0 + row) * DMODEL + kt + kq);
            float4 w4 = *(const float4*)(W + (size_t)(n0 + row) * DMODEL + kt + kq);
            As[row * APAD + P8(kq + 0)] = f2tf32(a4.x);
            As[row * APAD + P8(kq + 1)] = f2tf32(a4.y);
            As[row * APAD + P8(kq + 2)] = f2tf32(a4.z);
            As[row * APAD + P8(kq + 3)] = f2tf32(a4.w);
            Ws[row * APAD + P8(kq + 0)] = f2tf32(w4.x);
            Ws[row * APAD + P8(kq + 1)] = f2tf32(w4.y);
            Ws[row * APAD + P8(kq + 2)] = f2tf32(w4.z);
            Ws[row * APAD + P8(kq + 3)] = f2tf32(w4.w);
        }
        __syncthreads();

#pragma unroll
        for (int c = 0; c < 4; c++) {
            const int kb = c * 8;
            unsigned a0[4], a1[4], a2[4], a3[4];
#pragma unroll
            for (int mt = 0; mt < 4; mt++) {
                const int r = wm * 64 + mt * 16 + g;
                uint2 lo = *(const uint2*)&As[r * APAD + kb + 2 * th];
                uint2 hi = *(const uint2*)&As[(r + 8) * APAD + kb + 2 * th];
                a0[mt] = lo.x; a2[mt] = lo.y;
                a1[mt] = hi.x; a3[mt] = hi.y;
            }
#pragma unroll
            for (int nt = 0; nt < 4; nt++) {
                const int n = wn * 32 + nt * 8 + g;
                uint2 bb = *(const uint2*)&Ws[n * APAD + kb + 2 * th];
#pragma unroll
                for (int mt = 0; mt < 4; mt++)
                    mma_tf32(acc[mt][nt], a0[mt], a1[mt], a2[mt], a3[mt], bb.x, bb.y);
            }
        }
    }

    // epilogue
#pragma unroll
    for (int nt = 0; nt < 4; nt++) {
        const int n = n0 + wn * 32 + nt * 8 + 2 * th;
        const float bx = bias[n], by = bias[n + 1];
#pragma unroll
        for (int mt = 0; mt < 4; mt++) {
            const int m = m0 + wm * 64 + mt * 16 + g;
            float2 o0 = make_float2(acc[mt][nt][0] + bx, acc[mt][nt][1] + by);
            float2 o1 = make_float2(acc[mt][nt][2] + bx, acc[mt][nt][3] + by);
            *(float2*)(out + (size_t)m * DMODEL + n)       = o0;
            *(float2*)(out + (size_t)(m + 8) * DMODEL + n) = o1;
        }
    }
}

__global__ __launch_bounds__(256)
void proj3_kernel(const float* __restrict__ q, const float* __restrict__ k,
                  const float* __restrict__ v, const float* __restrict__ W,
                  const float* __restrict__ bias,
                  float* __restrict__ qp, float* __restrict__ kp,
                  float* __restrict__ vp)
{
    const float* A;
    float* out;
    if (blockIdx.z == 0)      { A = q; out = qp; }
    else if (blockIdx.z == 1) { A = k; out = kp; }
    else                      { A = v; out = vp; }
    gemm_mma_body(A, W, bias, out, blockIdx.y * 128, blockIdx.x * 128);
}

__global__ __launch_bounds__(256)
void gemm_kernel(const float* __restrict__ A, const float* __restrict__ W,
                 const float* __restrict__ bias, float* __restrict__ out)
{
    gemm_mma_body(A, W, bias, out, blockIdx.y * 128, blockIdx.x * 128);
}

// ============================================================================
// Flash attention with tf32 mma. Block = 128 q-rows, kv streamed in 64 tiles.
// 8 warps; each warp owns 16 q-rows x full 64 kv cols (softmax is in-warp).
// smem (u32 elements):
//   Qs [128][72]  q rows, p8-permuted d, pre-scaled by 1/8, tf32
//   Ks [64][72]   kv rows, p8-permuted d, tf32
//   Vs [64][72]   TRANSPOSED: Vs[dv][p8(c)], tf32
//   Ps [128][68]  P tile, natural cols, tf32
// ============================================================================
#define QKV_PAD 72   // 72 % 32 == 8
#define P_PAD   68   // 68 % 32 == 4 -> 4g+th bijective, conflict-free
#define QS_OFF  0
#define KS_OFF  (128 * QKV_PAD)
#define VS_OFF  (KS_OFF + 64 * QKV_PAD)
#define PS_OFF  (VS_OFF + 64 * QKV_PAD)
#define FA_SMEM_U32 (PS_OFF + 128 * P_PAD)

__global__ __launch_bounds__(256, 2)
void flash_attn_kernel(const float* __restrict__ qp,
                       const float* __restrict__ kp,
                       const float* __restrict__ vp,
                       float* __restrict__ att)
{
    extern __shared__ unsigned sm[];
    unsigned* Qs = sm + QS_OFF;
    unsigned* Ks = sm + KS_OFF;
    unsigned* Vs = sm + VS_OFF;
    unsigned* Ps = sm + PS_OFF;

    const int tid  = threadIdx.x;
    const int warp = tid >> 5;
    const int lane = tid & 31;
    const int g    = lane >> 2;
    const int th   = lane & 3;
    const int qr0  = warp * 16;            // this warp's q-row base (block-local)

    const int s0 = blockIdx.x * 128;
    const int h  = blockIdx.y;
    const int b  = blockIdx.z;
    const size_t base = (size_t)b * SEQ * DMODEL + (size_t)h * DHEAD;

    // ---- stage Q tile once (128 x 64), scaled by 1/8, tf32, p8 cols ----
#pragma unroll
    for (int i = 0; i < 8; i++) {
        const int idx = i * 256 + tid;     // 2048 float4 slots
        const int row = idx >> 4;          // 0..127
        const int kq  = (idx & 15) << 2;   // 0..60
        float4 v4 = *(const float4*)(qp + base + (size_t)(s0 + row) * DMODEL + kq);
        Qs[row * QKV_PAD + P8(kq + 0)] = f2tf32(v4.x * 0.125f);
        Qs[row * QKV_PAD + P8(kq + 1)] = f2tf32(v4.y * 0.125f);
        Qs[row * QKV_PAD + P8(kq + 2)] = f2tf32(v4.z * 0.125f);
        Qs[row * QKV_PAD + P8(kq + 3)] = f2tf32(v4.w * 0.125f);
    }

    float oacc[8][4];
#pragma unroll
    for (int nt = 0; nt < 8; nt++)
#pragma unroll
        for (int i = 0; i < 4; i++) oacc[nt][i] = 0.f;
    float mrun0 = -INFINITY, mrun1 = -INFINITY;
    float lrun0 = 0.f, lrun1 = 0.f;

    for (int kt = 0; kt < SEQ; kt += 64) {
        __syncthreads();   // previous tile's Ks/Vs reads done

        // ---- stage K (natural rows, p8 cols) and V (transposed, p8 cols) ----
#pragma unroll
        for (int i = 0; i < 4; i++) {
            const int idx = i * 256 + tid;   // 1024 float4 slots
            const int row = idx >> 4;        // 0..63
            const int kq  = (idx & 15) << 2;
            float4 k4 = *(const float4*)(kp + base + (size_t)(kt + row) * DMODEL + kq);
            Ks[row * QKV_PAD + P8(kq + 0)] = f2tf32(k4.x);
            Ks[row * QKV_PAD + P8(kq + 1)] = f2tf32(k4.y);
            Ks[row * QKV_PAD + P8(kq + 2)] = f2tf32(k4.z);
            Ks[row * QKV_PAD + P8(kq + 3)] = f2tf32(k4.w);
            float4 v4 = *(const float4*)(vp + base + (size_t)(kt + row) * DMODEL + kq);
            // transpose scatter with lane-rotated order to spread banks
#pragma unroll
            for (int jj = 0; jj < 4; jj++) {
                const int j = (jj + lane) & 3;
                const float val = (j == 0) ? v4.x : (j == 1) ? v4.y : (j == 2) ? v4.z : v4.w;
                Vs[(kq + j) * QKV_PAD + P8(row)] = f2tf32(val);
            }
        }
        __syncthreads();

        // ---- S = (Q/8) K^T  : warp computes 16 x 64 ----
        float sacc[8][4];
#pragma unroll
        for (int nt = 0; nt < 8; nt++)
#pragma unroll
            for (int i = 0; i < 4; i++) sacc[nt][i] = 0.f;

#pragma unroll
        for (int c = 0; c < 8; c++) {
            const int kb = c * 8;
            uint2 lo = *(const uint2*)&Qs[(qr0 + g) * QKV_PAD + kb + 2 * th];
            uint2 hi = *(const uint2*)&Qs[(qr0 + g + 8) * QKV_PAD + kb + 2 * th];
#pragma unroll
            for (int nt = 0; nt < 8; nt++) {
                uint2 bb = *(const uint2*)&Ks[(nt * 8 + g) * QKV_PAD + kb + 2 * th];
                mma_tf32(sacc[nt], lo.x, hi.x, lo.y, hi.y, bb.x, bb.y);
            }
        }

        // ---- online softmax (rows g and g+8 of this warp's 16) ----
        float mx0 = -INFINITY, mx1 = -INFINITY;
#pragma unroll
        for (int nt = 0; nt < 8; nt++) {
            mx0 = fmaxf(mx0, fmaxf(sacc[nt][0], sacc[nt][1]));
            mx1 = fmaxf(mx1, fmaxf(sacc[nt][2], sacc[nt][3]));
        }
        mx0 = fmaxf(mx0, __shfl_xor_sync(0xffffffffu, mx0, 1));
        mx0 = fmaxf(mx0, __shfl_xor_sync(0xffffffffu, mx0, 2));
        mx1 = fmaxf(mx1, __shfl_xor_sync(0xffffffffu, mx1, 1));
        mx1 = fmaxf(mx1, __shfl_xor_sync(0xffffffffu, mx1, 2));

        const float mnew0 = fmaxf(mrun0, mx0);
        const float mnew1 = fmaxf(mrun1, mx1);
        const float alpha0 = __expf(mrun0 - mnew0);
        const float alpha1 = __expf(mrun1 - mnew1);
        mrun0 = mnew0; mrun1 = mnew1;

        float ps0 = 0.f, ps1 = 0.f;
#pragma unroll
        for (int nt = 0; nt < 8; nt++) {
            sacc[nt][0] = __expf(sacc[nt][0] - mnew0);
            sacc[nt][1] = __expf(sacc[nt][1] - mnew0);
            sacc[nt][2] = __expf(sacc[nt][2] - mnew1);
            sacc[nt][3] = __expf(sacc[nt][3] - mnew1);
            ps0 += sacc[nt][0] + sacc[nt][1];
            ps1 += sacc[nt][2] + sacc[nt][3];
        }
        ps0 += __shfl_xor_sync(0xffffffffu, ps0, 1);
        ps0 += __shfl_xor_sync(0xffffffffu, ps0, 2);
        ps1 += __shfl_xor_sync(0xffffffffu, ps1, 1);
        ps1 += __shfl_xor_sync(0xffffffffu, ps1, 2);
        lrun0 = lrun0 * alpha0 + ps0;
        lrun1 = lrun1 * alpha1 + ps1;

#pragma unroll
        for (int nt = 0; nt < 8; nt++) {
            oacc[nt][0] *= alpha0; oacc[nt][1] *= alpha0;
            oacc[nt][2] *= alpha1; oacc[nt][3] *= alpha1;
        }

        // ---- stage P (warp-private 16 rows, natural cols, tf32) ----
#pragma unroll
        for (int nt = 0; nt < 8; nt++) {
            const int col = nt * 8 + 2 * th;
            uint2 p0 = make_uint2(f2tf32(sacc[nt][0]), f2tf32(sacc[nt][1]));
            uint2 p1 = make_uint2(f2tf32(sacc[nt][2]), f2tf32(sacc[nt][3]));
            *(uint2*)&Ps[(qr0 + g) * P_PAD + col]     = p0;
            *(uint2*)&Ps[(qr0 + g + 8) * P_PAD + col] = p1;
        }
        __syncwarp();

        // ---- O += P @ V ----
#pragma unroll
        for (int c = 0; c < 8; c++) {
            const int cb = c * 8;
            const unsigned pa0 = Ps[(qr0 + g) * P_PAD + cb + th];
            const unsigned pa2 = Ps[(qr0 + g) * P_PAD + cb + th + 4];
            const unsigned pa1 = Ps[(qr0 + g + 8) * P_PAD + cb + th];
            const unsigned pa3 = Ps[(qr0 + g + 8) * P_PAD + cb + th + 4];
#pragma unroll
            for (int nt = 0; nt < 8; nt++) {
                uint2 vb = *(const uint2*)&Vs[(nt * 8 + g) * QKV_PAD + cb + 2 * th];
                mma_tf32(oacc[nt], pa0, pa1, pa2, pa3, vb.x, vb.y);
            }
        }
    }

    // ---- epilogue ----
    const float invl0 = 1.0f / lrun0;
    const float invl1 = 1.0f / lrun1;
    const int row0 = s0 + qr0 + g;
    const int row1 = row0 + 8;
#pragma unroll
    for (int nt = 0; nt < 8; nt++) {
        const int dv = nt * 8 + 2 * th;
        float2 o0 = make_float2(oacc[nt][0] * invl0, oacc[nt][1] * invl0);
        float2 o1 = make_float2(oacc[nt][2] * invl1, oacc[nt][3] * invl1);
        *(float2*)(att + base + (size_t)row0 * DMODEL + dv) = o0;
        *(float2*)(att + base + (size_t)row1 * DMODEL + dv) = o1;
    }
}

// ---------------- host launcher ---------------------------------------------
extern "C" void kernel_launch(void* const* d_in, const int* in_sizes, int n_in,
                              void* d_out, int out_size)
{
    const float* q    = (const float*)d_in[0];
    const float* k    = (const float*)d_in[1];
    const float* v    = (const float*)d_in[2];
    const float* Wq_w = (const float*)d_in[3];
    const float* Wq_b = (const float*)d_in[4];
    const float* Wc_w = (const float*)d_in[5];
    const float* Wc_b = (const float*)d_in[6];
    float* out = (float*)d_out;

    float *qp, *kp, *vp, *attp;
    cudaGetSymbolAddress((void**)&qp,   g_qp);
    cudaGetSymbolAddress((void**)&kp,   g_kp);
    cudaGetSymbolAddress((void**)&vp,   g_vp);
    cudaGetSymbolAddress((void**)&attp, g_att);

    // three input projections (all use Wq), batched over grid.z
    dim3 pgrid(DMODEL / 128, MTOT / 128, 3);    // (4, 32, 3)
    proj3_kernel<<<pgrid, 256>>>(q, k, v, Wq_w, Wq_b, qp, kp, vp);

    // flash attention
    const int fa_smem = FA_SMEM_U32 * (int)sizeof(unsigned);   // 108544 B
    cudaFuncSetAttribute(flash_attn_kernel,
                         cudaFuncAttributeMaxDynamicSharedMemorySize, fa_smem);
    dim3 fgrid(SEQ / 128, NHEADS, BATCH);       // (16, 8, 2)
    flash_attn_kernel<<<fgrid, 256, fa_smem>>>(qp, kp, vp, attp);

    // output projection
    dim3 ogrid(DMODEL / 128, MTOT / 128);       // (4, 32)
    gemm_kernel<<<ogrid, 256>>>(attp, Wc_w, Wc_b, out);
}

// round 4
// speedup vs baseline: 5.8172x; 1.7827x over previous
#include <cuda_runtime.h>
#include <cuda_fp16.h>
#include <math.h>

// Problem constants
#define BATCH   2
#define SEQ     2048
#define DMODEL  512
#define NHEADS  8
#define DHEAD   64
#define MTOT    (BATCH * SEQ)

// ---------------- scratch (static device arrays; no allocation) -------------
__device__ float g_qp [BATCH * SEQ * DMODEL];
__device__ float g_kp [BATCH * SEQ * DMODEL];
__device__ float g_vp [BATCH * SEQ * DMODEL];
__device__ float g_att[BATCH * SEQ * DMODEL];

// ---------------- fp16 mma helpers ------------------------------------------
__device__ __forceinline__ unsigned h2(float lo, float hi) {
    __half2 h = __floats2half2_rn(lo, hi);
    return *(unsigned*)&h;
}

// D = A(16x16) * B(16x8) + D, fp16 in, fp32 accum
__device__ __forceinline__ void mma_f16(float c[4],
                                        unsigned a0, unsigned a1,
                                        unsigned a2, unsigned a3,
                                        unsigned b0, unsigned b1) {
    asm volatile(
        "mma.sync.aligned.m16n8k16.row.col.f32.f16.f16.f32 "
        "{%0,%1,%2,%3}, {%4,%5,%6,%7}, {%8,%9}, {%0,%1,%2,%3};"
        : "+f"(c[0]), "+f"(c[1]), "+f"(c[2]), "+f"(c[3])
        : "r"(a0), "r"(a1), "r"(a2), "r"(a3), "r"(b0), "r"(b1));
}

// pair-permutation within 8-pair chunks: (p, p+4) -> adjacent -> one LDS.64
#define P8(k) (((k) & ~7) | (((k) & 3) << 1) | (((k) >> 2) & 1))

// ============================================================================
// fp16 GEMM: out[m][n] = sum_k A[m][k]*W[n][k] + bias[n]
// Block 128m x 128n, BK=32 (2 k16 chunks), 8 warps (2m x 4n), warp 64m x 32n.
// Double-buffered smem, register prefetch, one __syncthreads per BK iter.
// smem rows hold 16 f16x2 pairs, P8-permuted, pad to 24 u32.
// ============================================================================
#define GPAD 24
#define G_STAGE (128 * GPAD)

__device__ __forceinline__ void gemm_load(const float* __restrict__ A,
                                          const float* __restrict__ W,
                                          int m0, int n0, int kt, int tid,
                                          float4 af[4], float4 wf[4])
{
#pragma unroll
    for (int i = 0; i < 4; i++) {
        const int idx = i * 256 + tid;
        const int row = idx >> 3;            // 0..127
        const int q4  = idx & 7;             // float4 col
        af[i] = *(const float4*)(A + (size_t)(m0 + row) * DMODEL + kt + 4 * q4);
        wf[i] = *(const float4*)(W + (size_t)(n0 + row) * DMODEL + kt + 4 * q4);
    }
}

__device__ __forceinline__ void gemm_store(unsigned* As, unsigned* Ws, int tid,
                                           const float4 af[4], const float4 wf[4])
{
#pragma unroll
    for (int i = 0; i < 4; i++) {
        const int idx = i * 256 + tid;
        const int row = idx >> 3;
        const int q4  = idx & 7;
        As[row * GPAD + P8(2 * q4)]     = h2(af[i].x, af[i].y);
        As[row * GPAD + P8(2 * q4 + 1)] = h2(af[i].z, af[i].w);
        Ws[row * GPAD + P8(2 * q4)]     = h2(wf[i].x, wf[i].y);
        Ws[row * GPAD + P8(2 * q4 + 1)] = h2(wf[i].z, wf[i].w);
    }
}

__device__ __forceinline__ void gemm_mma_body(const float* __restrict__ A,
                                              const float* __restrict__ W,
                                              const float* __restrict__ bias,
                                              float* __restrict__ out,
                                              int m0, int n0)
{
    extern __shared__ unsigned gsm[];
    unsigned* As = gsm;                      // [2][128*GPAD]
    unsigned* Ws = gsm + 2 * G_STAGE;        // [2][128*GPAD]

    const int tid  = threadIdx.x;
    const int warp = tid >> 5;
    const int lane = tid & 31;
    const int g    = lane >> 2;
    const int th   = lane & 3;
    const int wm   = warp >> 2;
    const int wn   = warp & 3;

    float acc[4][4][4];
#pragma unroll
    for (int mt = 0; mt < 4; mt++)
#pragma unroll
        for (int nt = 0; nt < 4; nt++)
#pragma unroll
            for (int i = 0; i < 4; i++) acc[mt][nt][i] = 0.f;

    // prologue: stage tile 0
    float4 af[4], wf[4];
    gemm_load(A, W, m0, n0, 0, tid, af, wf);
    gemm_store(As, Ws, tid, af, wf);

    const int NIT = DMODEL / 32;             // 16
    for (int it = 0; it < NIT; it++) {
        __syncthreads();
        const int s = it & 1;
        unsigned* Ac = As + s * G_STAGE;
        unsigned* Wc = Ws + s * G_STAGE;
        const bool more = (it + 1 < NIT);

        if (more) gemm_load(A, W, m0, n0, (it + 1) * 32, tid, af, wf);

#pragma unroll
        for (int c = 0; c < 2; c++) {
            const int kb = c * 8 + 2 * th;
            unsigned a0[4], a1[4], a2[4], a3[4];
#pragma unroll
            for (int mt = 0; mt < 4; mt++) {
                const int r = wm * 64 + mt * 16 + g;
                uint2 lo = *(const uint2*)&Ac[r * GPAD + kb];
                uint2 hi = *(const uint2*)&Ac[(r + 8) * GPAD + kb];
                a0[mt] = lo.x; a2[mt] = lo.y;
                a1[mt] = hi.x; a3[mt] = hi.y;
            }
#pragma unroll
            for (int nt = 0; nt < 4; nt++) {
                const int n = wn * 32 + nt * 8 + g;
                uint2 bb = *(const uint2*)&Wc[n * GPAD + kb];
#pragma unroll
                for (int mt = 0; mt < 4; mt++)
                    mma_f16(acc[mt][nt], a0[mt], a1[mt], a2[mt], a3[mt], bb.x, bb.y);
            }
        }

        if (more) gemm_store(As + (s ^ 1) * G_STAGE, Ws + (s ^ 1) * G_STAGE, tid, af, wf);
    }

    // epilogue
#pragma unroll
    for (int nt = 0; nt < 4; nt++) {
        const int n = n0 + wn * 32 + nt * 8 + 2 * th;
        const float bx = bias[n], by = bias[n + 1];
#pragma unroll
        for (int mt = 0; mt < 4; mt++) {
            const int m = m0 + wm * 64 + mt * 16 + g;
            float2 o0 = make_float2(acc[mt][nt][0] + bx, acc[mt][nt][1] + by);
            float2 o1 = make_float2(acc[mt][nt][2] + bx, acc[mt][nt][3] + by);
            *(float2*)(out + (size_t)m * DMODEL + n)       = o0;
            *(float2*)(out + (size_t)(m + 8) * DMODEL + n) = o1;
        }
    }
}

#define GEMM_SMEM (4 * G_STAGE * (int)sizeof(unsigned))   // 49152 B

__global__ __launch_bounds__(256, 2)
void proj3_kernel(const float* __restrict__ q, const float* __restrict__ k,
                  const float* __restrict__ v, const float* __restrict__ W,
                  const float* __restrict__ bias,
                  float* __restrict__ qp, float* __restrict__ kp,
                  float* __restrict__ vp)
{
    const float* A;
    float* out;
    if (blockIdx.z == 0)      { A = q; out = qp; }
    else if (blockIdx.z == 1) { A = k; out = kp; }
    else                      { A = v; out = vp; }
    gemm_mma_body(A, W, bias, out, blockIdx.y * 128, blockIdx.x * 128);
}

__global__ __launch_bounds__(256, 2)
void gemm_kernel(const float* __restrict__ A, const float* __restrict__ W,
                 const float* __restrict__ bias, float* __restrict__ out)
{
    gemm_mma_body(A, W, bias, out, blockIdx.y * 128, blockIdx.x * 128);
}

// ============================================================================
// Flash attention, fp16 mma. Block = 128 q-rows; kv streamed in 64-row tiles,
// double-buffered. 8 warps; warp owns 16 q-rows x full 64 kv (in-warp softmax).
// P never touches smem: S accumulators repack into PV A-fragments.
//   Qs [128][FPAD]  f16x2 d-pairs, P8, pre-scaled by 1/8
//   Ks [2][64][FPAD]  f16x2 d-pairs, P8 (natural rows)
//   Vs [2][64][FPAD]  TRANSPOSED: Vs[dv][kv-pair], P8 on pair index
// ============================================================================
#define FPAD 40
#define F_Q     (128 * FPAD)
#define F_STAGE (64 * FPAD)
#define FA_SMEM ((F_Q + 4 * F_STAGE) * (int)sizeof(unsigned))   // 61440 B

__device__ __forceinline__ void fa_load_k(const float* __restrict__ kp,
                                          size_t base, int kt, int tid, float4 kf[4])
{
#pragma unroll
    for (int i = 0; i < 4; i++) {
        const int idx = i * 256 + tid;
        const int row = idx >> 4;            // 0..63
        const int q4  = idx & 15;
        kf[i] = *(const float4*)(kp + base + (size_t)(kt + row) * DMODEL + 4 * q4);
    }
}

__device__ __forceinline__ void fa_store_k(unsigned* Ks, int tid, const float4 kf[4])
{
#pragma unroll
    for (int i = 0; i < 4; i++) {
        const int idx = i * 256 + tid;
        const int row = idx >> 4;
        const int q4  = idx & 15;
        Ks[row * FPAD + P8(2 * q4)]     = h2(kf[i].x, kf[i].y);
        Ks[row * FPAD + P8(2 * q4 + 1)] = h2(kf[i].z, kf[i].w);
    }
}

// V loader: thread slot (rp=lane, dg=i*8+warp) loads rows 2rp,2rp+1 at dv 4dg..+3
__device__ __forceinline__ void fa_load_v(const float* __restrict__ vp,
                                          size_t base, int kt, int warp, int lane,
                                          float4 v0[2], float4 v1[2])
{
#pragma unroll
    for (int i = 0; i < 2; i++) {
        const int dg = i * 8 + warp;
        const float* p = vp + base + (size_t)(kt + 2 * lane) * DMODEL + 4 * dg;
        v0[i] = *(const float4*)(p);
        v1[i] = *(const float4*)(p + DMODEL);
    }
}

__device__ __forceinline__ void fa_store_v(unsigned* Vs, int warp, int lane,
                                           const float4 v0[2], const float4 v1[2])
{
#pragma unroll
    for (int i = 0; i < 2; i++) {
        const int dg = i * 8 + warp;
        const int pp = P8(lane);             // kv pair position
        Vs[(dg * 4 + 0) * FPAD + pp] = h2(v0[i].x, v1[i].x);
        Vs[(dg * 4 + 1) * FPAD + pp] = h2(v0[i].y, v1[i].y);
        Vs[(dg * 4 + 2) * FPAD + pp] = h2(v0[i].z, v1[i].z);
        Vs[(dg * 4 + 3) * FPAD + pp] = h2(v0[i].w, v1[i].w);
    }
}

__global__ __launch_bounds__(256, 2)
void flash_attn_kernel(const float* __restrict__ qp,
                       const float* __restrict__ kp,
                       const float* __restrict__ vp,
                       float* __restrict__ att)
{
    extern __shared__ unsigned sm[];
    unsigned* Qs = sm;
    unsigned* Ks = sm + F_Q;                 // [2][64*FPAD]
    unsigned* Vs = Ks + 2 * F_STAGE;         // [2][64*FPAD]

    const int tid  = threadIdx.x;
    const int warp = tid >> 5;
    const int lane = tid & 31;
    const int g    = lane >> 2;
    const int th   = lane & 3;
    const int qr0  = warp * 16;

    const int s0 = blockIdx.x * 128;
    const int h  = blockIdx.y;
    const int b  = blockIdx.z;
    const size_t base = (size_t)b * SEQ * DMODEL + (size_t)h * DHEAD;

    // ---- stage Q once (128 x 64), scaled 1/8, f16x2 pairs, P8 ----
#pragma unroll
    for (int i = 0; i < 8; i++) {
        const int idx = i * 256 + tid;
        const int row = idx >> 4;
        const int q4  = idx & 15;
        float4 v4 = *(const float4*)(qp + base + (size_t)(s0 + row) * DMODEL + 4 * q4);
        Qs[row * FPAD + P8(2 * q4)]     = h2(v4.x * 0.125f, v4.y * 0.125f);
        Qs[row * FPAD + P8(2 * q4 + 1)] = h2(v4.z * 0.125f, v4.w * 0.125f);
    }

    // ---- prologue: stage K/V tile 0 ----
    {
        float4 kf[4], v0[2], v1[2];
        fa_load_k(kp, base, 0, tid, kf);
        fa_load_v(vp, base, 0, warp, lane, v0, v1);
        fa_store_k(Ks, tid, kf);
        fa_store_v(Vs, warp, lane, v0, v1);
    }

    float oacc[8][4];
#pragma unroll
    for (int nt = 0; nt < 8; nt++)
#pragma unroll
        for (int i = 0; i < 4; i++) oacc[nt][i] = 0.f;
    float mrun0 = -INFINITY, mrun1 = -INFINITY;
    float lrun0 = 0.f, lrun1 = 0.f;

    const int NIT = SEQ / 64;                // 32
    for (int it = 0; it < NIT; it++) {
        __syncthreads();
        const int s = it & 1;
        unsigned* Kc = Ks + s * F_STAGE;
        unsigned* Vc = Vs + s * F_STAGE;
        const bool more = (it + 1 < NIT);

        float4 kf[4];
        if (more) fa_load_k(kp, base, (it + 1) * 64, tid, kf);

        // ---- S = (Q/8) K^T : 4 k16 chunks x 8 n-blocks ----
        float sacc[8][4];
#pragma unroll
        for (int nt = 0; nt < 8; nt++)
#pragma unroll
            for (int i = 0; i < 4; i++) sacc[nt][i] = 0.f;

#pragma unroll
        for (int c = 0; c < 4; c++) {
            const int kb = c * 8 + 2 * th;
            uint2 qa = *(const uint2*)&Qs[(qr0 + g) * FPAD + kb];
            uint2 qb = *(const uint2*)&Qs[(qr0 + g + 8) * FPAD + kb];
#pragma unroll
            for (int nt = 0; nt < 8; nt++) {
                uint2 bb = *(const uint2*)&Kc[(nt * 8 + g) * FPAD + kb];
                mma_f16(sacc[nt], qa.x, qb.x, qa.y, qb.y, bb.x, bb.y);
            }
        }

        float4 v0[2], v1[2];
        if (more) fa_load_v(vp, base, (it + 1) * 64, warp, lane, v0, v1);

        // ---- online softmax (rows g, g+8), reduce across th (xor 1,2) ----
        float mx0 = -INFINITY, mx1 = -INFINITY;
#pragma unroll
        for (int nt = 0; nt < 8; nt++) {
            mx0 = fmaxf(mx0, fmaxf(sacc[nt][0], sacc[nt][1]));
            mx1 = fmaxf(mx1, fmaxf(sacc[nt][2], sacc[nt][3]));
        }
        mx0 = fmaxf(mx0, __shfl_xor_sync(0xffffffffu, mx0, 1));
        mx0 = fmaxf(mx0, __shfl_xor_sync(0xffffffffu, mx0, 2));
        mx1 = fmaxf(mx1, __shfl_xor_sync(0xffffffffu, mx1, 1));
        mx1 = fmaxf(mx1, __shfl_xor_sync(0xffffffffu, mx1, 2));

        const float mnew0 = fmaxf(mrun0, mx0);
        const float mnew1 = fmaxf(mrun1, mx1);
        const float alpha0 = __expf(mrun0 - mnew0);
        const float alpha1 = __expf(mrun1 - mnew1);
        mrun0 = mnew0; mrun1 = mnew1;

        float ps0 = 0.f, ps1 = 0.f;
#pragma unroll
        for (int nt = 0; nt < 8; nt++) {
            sacc[nt][0] = __expf(sacc[nt][0] - mnew0);
            sacc[nt][1] = __expf(sacc[nt][1] - mnew0);
            sacc[nt][2] = __expf(sacc[nt][2] - mnew1);
            sacc[nt][3] = __expf(sacc[nt][3] - mnew1);
            ps0 += sacc[nt][0] + sacc[nt][1];
            ps1 += sacc[nt][2] + sacc[nt][3];
        }
        ps0 += __shfl_xor_sync(0xffffffffu, ps0, 1);
        ps0 += __shfl_xor_sync(0xffffffffu, ps0, 2);
        ps1 += __shfl_xor_sync(0xffffffffu, ps1, 1);
        ps1 += __shfl_xor_sync(0xffffffffu, ps1, 2);
        lrun0 = lrun0 * alpha0 + ps0;
        lrun1 = lrun1 * alpha1 + ps1;

#pragma unroll
        for (int nt = 0; nt < 8; nt++) {
            oacc[nt][0] *= alpha0; oacc[nt][1] *= alpha0;
            oacc[nt][2] *= alpha1; oacc[nt][3] *= alpha1;
        }

        // ---- O += P @ V : P repacked from S accumulators (no smem) ----
#pragma unroll
        for (int c = 0; c < 4; c++) {
            const unsigned pa0 = h2(sacc[2 * c][0],     sacc[2 * c][1]);
            const unsigned pa1 = h2(sacc[2 * c][2],     sacc[2 * c][3]);
            const unsigned pa2 = h2(sacc[2 * c + 1][0], sacc[2 * c + 1][1]);
            const unsigned pa3 = h2(sacc[2 * c + 1][2], sacc[2 * c + 1][3]);
            const int kb = c * 8 + 2 * th;
#pragma unroll
            for (int nt = 0; nt < 8; nt++) {
                uint2 vb = *(const uint2*)&Vc[(nt * 8 + g) * FPAD + kb];
                mma_f16(oacc[nt], pa0, pa1, pa2, pa3, vb.x, vb.y);
            }
        }

        // ---- stage next tile ----
        if (more) {
            fa_store_k(Ks + (s ^ 1) * F_STAGE, tid, kf);
            fa_store_v(Vs + (s ^ 1) * F_STAGE, warp, lane, v0, v1);
        }
    }

    // ---- epilogue ----
    const float invl0 = 1.0f / lrun0;
    const float invl1 = 1.0f / lrun1;
    const int row0 = s0 + qr0 + g;
    const int row1 = row0 + 8;
#pragma unroll
    for (int nt = 0; nt < 8; nt++) {
        const int dv = nt * 8 + 2 * th;
        float2 o0 = make_float2(oacc[nt][0] * invl0, oacc[nt][1] * invl0);
        float2 o1 = make_float2(oacc[nt][2] * invl1, oacc[nt][3] * invl1);
        *(float2*)(att + base + (size_t)row0 * DMODEL + dv) = o0;
        *(float2*)(att + base + (size_t)row1 * DMODEL + dv) = o1;
    }
}

// ---------------- host launcher ---------------------------------------------
extern "C" void kernel_launch(void* const* d_in, const int* in_sizes, int n_in,
                              void* d_out, int out_size)
{
    const float* q    = (const float*)d_in[0];
    const float* k    = (const float*)d_in[1];
    const float* v    = (const float*)d_in[2];
    const float* Wq_w = (const float*)d_in[3];
    const float* Wq_b = (const float*)d_in[4];
    const float* Wc_w = (const float*)d_in[5];
    const float* Wc_b = (const float*)d_in[6];
    float* out = (float*)d_out;

    float *qp, *kp, *vp, *attp;
    cudaGetSymbolAddress((void**)&qp,   g_qp);
    cudaGetSymbolAddress((void**)&kp,   g_kp);
    cudaGetSymbolAddress((void**)&vp,   g_vp);
    cudaGetSymbolAddress((void**)&attp, g_att);

    cudaFuncSetAttribute(proj3_kernel,
                         cudaFuncAttributeMaxDynamicSharedMemorySize, GEMM_SMEM);
    cudaFuncSetAttribute(gemm_kernel,
                         cudaFuncAttributeMaxDynamicSharedMemorySize, GEMM_SMEM);
    cudaFuncSetAttribute(flash_attn_kernel,
                         cudaFuncAttributeMaxDynamicSharedMemorySize, FA_SMEM);

    // three input projections (all use Wq), batched over grid.z
    dim3 pgrid(DMODEL / 128, MTOT / 128, 3);    // (4, 32, 3)
    proj3_kernel<<<pgrid, 256, GEMM_SMEM>>>(q, k, v, Wq_w, Wq_b, qp, kp, vp);

    // flash attention
    dim3 fgrid(SEQ / 128, NHEADS, BATCH);       // (16, 8, 2)
    flash_attn_kernel<<<fgrid, 256, FA_SMEM>>>(qp, kp, vp, attp);

    // output projection
    dim3 ogrid(DMODEL / 128, MTOT / 128);       // (4, 32)
    gemm_kernel<<<ogrid, 256, GEMM_SMEM>>>(attp, Wc_w, Wc_b, out);
}

// round 6
// speedup vs baseline: 8.7166x; 1.4984x over previous
#include <cuda_runtime.h>
#include <cuda_fp16.h>
#include <cstdint>
#include <math.h>

// Problem constants
#define BATCH   2
#define SEQ     2048
#define DMODEL  512
#define NHEADS  8
#define DHEAD   64
#define MTOT    (BATCH * SEQ)

// ---------------- scratch (static device arrays; no allocation) -------------
__device__ __half g_qh [MTOT * DMODEL];     // half copies of inputs
__device__ __half g_kh [MTOT * DMODEL];
__device__ __half g_vh [MTOT * DMODEL];
__device__ __half g_Wqh[DMODEL * DMODEL];
__device__ __half g_Wch[DMODEL * DMODEL];
__device__ __half g_qp [MTOT * DMODEL];     // projection outputs (q pre-scaled by 1/8)
__device__ __half g_kp [MTOT * DMODEL];
__device__ __half g_vp [MTOT * DMODEL];
__device__ __half g_att[MTOT * DMODEL];     // attention output

// ---------------- helpers ----------------------------------------------------
__device__ __forceinline__ unsigned h2u(float lo, float hi) {
    __half2 h = __floats2half2_rn(lo, hi);
    return *(unsigned*)&h;
}

__device__ __forceinline__ void mma_f16(float c[4],
                                        unsigned a0, unsigned a1,
                                        unsigned a2, unsigned a3,
                                        unsigned b0, unsigned b1) {
    asm volatile(
        "mma.sync.aligned.m16n8k16.row.col.f32.f16.f16.f32 "
        "{%0,%1,%2,%3}, {%4,%5,%6,%7}, {%8,%9}, {%0,%1,%2,%3};"
        : "+f"(c[0]), "+f"(c[1]), "+f"(c[2]), "+f"(c[3])
        : "r"(a0), "r"(a1), "r"(a2), "r"(a3), "r"(b0), "r"(b1));
}

__device__ __forceinline__ uint32_t cvta_s(const void* p) {
    return (uint32_t)__cvta_generic_to_shared(p);
}

#define CP16(dst, src) \
    asm volatile("cp.async.cg.shared.global [%0], [%1], 16;" :: "r"(dst), "l"(src))
#define CPCOMMIT() asm volatile("cp.async.commit_group;")
#define CPWAIT(n)  asm volatile("cp.async.wait_group %0;" :: "n"(n))

__device__ __forceinline__ void ldsm_x4(unsigned& r0, unsigned& r1,
                                        unsigned& r2, unsigned& r3, uint32_t addr) {
    asm volatile("ldmatrix.sync.aligned.m8n8.x4.shared.b16 {%0,%1,%2,%3}, [%4];"
                 : "=r"(r0), "=r"(r1), "=r"(r2), "=r"(r3) : "r"(addr));
}
__device__ __forceinline__ void ldsm_x4t(unsigned& r0, unsigned& r1,
                                         unsigned& r2, unsigned& r3, uint32_t addr) {
    asm volatile("ldmatrix.sync.aligned.m8n8.x4.trans.shared.b16 {%0,%1,%2,%3}, [%4];"
                 : "=r"(r0), "=r"(r1), "=r"(r2), "=r"(r3) : "r"(addr));
}

// All smem tiles: 128B rows (64 halves), swizzle chunk c -> c ^ (row & 7).
// Non-trans fragment address (A/B m16 or n16 block at row R, k16 chunk pair c0):
__device__ __forceinline__ uint32_t lda_nt(uint32_t base, int R, int c0, int lane) {
    const int r = R + (lane & 7) + (lane & 8);
    const int c = c0 + (lane >> 4);
    return base + (r << 7) + ((c ^ (r & 7)) << 4);
}
// Trans fragment address (V): rows = kv KB.., cols = dv chunk c0..
__device__ __forceinline__ uint32_t lda_tr(uint32_t base, int KB, int c0, int lane) {
    const int r = KB + ((lane >> 1) & 8) + (lane & 7);
    const int c = c0 + ((lane >> 3) & 1);
    return base + (r << 7) + ((c ^ (r & 7)) << 4);
}

// ---------------- conversion kernels -----------------------------------------
__global__ __launch_bounds__(256)
void cvt3_kernel(const float* __restrict__ q, const float* __restrict__ k,
                 const float* __restrict__ v,
                 __half* __restrict__ qh, __half* __restrict__ kh,
                 __half* __restrict__ vh)
{
    const float* s; __half* d;
    if (blockIdx.z == 0)      { s = q; d = qh; }
    else if (blockIdx.z == 1) { s = k; d = kh; }
    else                      { s = v; d = vh; }
    const size_t i = ((size_t)blockIdx.x * 256 + threadIdx.x) * 8;
    float4 a = *(const float4*)(s + i);
    float4 b = *(const float4*)(s + i + 4);
    uint4 o;
    o.x = h2u(a.x, a.y); o.y = h2u(a.z, a.w);
    o.z = h2u(b.x, b.y); o.w = h2u(b.z, b.w);
    *(uint4*)(d + i) = o;
}

__global__ __launch_bounds__(256)
void cvtW_kernel(const float* __restrict__ Wq, const float* __restrict__ Wc,
                 __half* __restrict__ Wqh, __half* __restrict__ Wch)
{
    const float* s = blockIdx.z == 0 ? Wq : Wc;
    __half* d      = blockIdx.z == 0 ? Wqh : Wch;
    const size_t i = ((size_t)blockIdx.x * 256 + threadIdx.x) * 8;
    float4 a = *(const float4*)(s + i);
    float4 b = *(const float4*)(s + i + 4);
    uint4 o;
    o.x = h2u(a.x, a.y); o.y = h2u(a.z, a.w);
    o.z = h2u(b.x, b.y); o.w = h2u(b.z, b.w);
    *(uint4*)(d + i) = o;
}

// ============================================================================
// half GEMM: acc[m][n] = sum_k A[m][k]*W[n][k]   (A, W half, k-major)
// Block 128m x 128n, BK=64, 3-stage cp.async pipeline, 8 warps (2m x 4n),
// warp tile 64m x 32n. ldmatrix fragment feed.
// smem stage: A 16KB + W 16KB; 3 stages = 96KB.
// ============================================================================
#define G_STG 0x8000           // 32KB per stage (A+W)
#define GEMM_SMEM (3 * G_STG)  // 98304 B

__device__ __forceinline__ void g_stage(uint32_t sA, uint32_t sW,
                                        const __half* __restrict__ A,
                                        const __half* __restrict__ W,
                                        int m0, int n0, int kt, int tid)
{
#pragma unroll
    for (int i = 0; i < 4; i++) {
        const int idx = i * 256 + tid;
        const int r = idx >> 3;
        const int c = idx & 7;
        const uint32_t off = (r << 7) + ((c ^ (r & 7)) << 4);
        CP16(sA + off, A + (size_t)(m0 + r) * DMODEL + kt + c * 8);
        CP16(sW + off, W + (size_t)(n0 + r) * DMODEL + kt + c * 8);
    }
}

__device__ __forceinline__ void gemm_core(const __half* __restrict__ A,
                                          const __half* __restrict__ W,
                                          int m0, int n0,
                                          float acc[4][4][4])
{
    extern __shared__ __align__(1024) unsigned char smraw[];
    const uint32_t sbase = cvta_s(smraw);
    const int tid  = threadIdx.x;
    const int warp = tid >> 5;
    const int lane = tid & 31;
    const int wm   = warp >> 2;
    const int wn   = warp & 3;

#pragma unroll
    for (int mt = 0; mt < 4; mt++)
#pragma unroll
        for (int nt = 0; nt < 4; nt++)
#pragma unroll
            for (int i = 0; i < 4; i++) acc[mt][nt][i] = 0.f;

    g_stage(sbase,         sbase + 0x4000,         A, W, m0, n0, 0,  tid); CPCOMMIT();
    g_stage(sbase + G_STG, sbase + G_STG + 0x4000, A, W, m0, n0, 64, tid); CPCOMMIT();

    const int NIT = DMODEL / 64;   // 8
    for (int it = 0; it < NIT; it++) {
        if (it == NIT - 1) { CPWAIT(0); } else { CPWAIT(1); }
        __syncthreads();
        if (it + 2 < NIT) {
            const uint32_t sn = sbase + ((it + 2) % 3) * G_STG;
            g_stage(sn, sn + 0x4000, A, W, m0, n0, (it + 2) * 64, tid);
            CPCOMMIT();
        }
        const uint32_t sA = sbase + (it % 3) * G_STG;
        const uint32_t sW = sA + 0x4000;

#pragma unroll
        for (int kk = 0; kk < 4; kk++) {
            unsigned a[4][4];
#pragma unroll
            for (int mt = 0; mt < 4; mt++)
                ldsm_x4(a[mt][0], a[mt][1], a[mt][2], a[mt][3],
                        lda_nt(sA, wm * 64 + mt * 16, kk * 2, lane));
            unsigned bf[2][4];
#pragma unroll
            for (int np = 0; np < 2; np++)
                ldsm_x4(bf[np][0], bf[np][1], bf[np][2], bf[np][3],
                        lda_nt(sW, wn * 32 + np * 16, kk * 2, lane));
#pragma unroll
            for (int nt = 0; nt < 4; nt++) {
                const int np = nt >> 1, sb = nt & 1;
#pragma unroll
                for (int mt = 0; mt < 4; mt++)
                    mma_f16(acc[mt][nt], a[mt][0], a[mt][1], a[mt][2], a[mt][3],
                            bf[np][sb], bf[np][sb + 2]);
            }
        }
    }
}

// Projections: 3 GEMMs (q,k,v @ Wq), half output; q output pre-scaled by 1/8.
__global__ __launch_bounds__(256, 2)
void proj3_kernel(const __half* __restrict__ qh, const __half* __restrict__ kh,
                  const __half* __restrict__ vh, const __half* __restrict__ W,
                  const float* __restrict__ bias,
                  __half* __restrict__ qp, __half* __restrict__ kp,
                  __half* __restrict__ vp)
{
    const __half* A; __half* out; float osc;
    if (blockIdx.z == 0)      { A = qh; out = qp; osc = 0.125f; }
    else if (blockIdx.z == 1) { A = kh; out = kp; osc = 1.0f;   }
    else                      { A = vh; out = vp; osc = 1.0f;   }

    const int m0 = blockIdx.y * 128;
    const int n0 = blockIdx.x * 128;
    float acc[4][4][4];
    gemm_core(A, W, m0, n0, acc);

    const int warp = threadIdx.x >> 5;
    const int lane = threadIdx.x & 31;
    const int g = lane >> 2, th = lane & 3;
    const int wm = warp >> 2, wn = warp & 3;

#pragma unroll
    for (int nt = 0; nt < 4; nt++) {
        const int n = n0 + wn * 32 + nt * 8 + 2 * th;
        const float bx = bias[n], by = bias[n + 1];
#pragma unroll
        for (int mt = 0; mt < 4; mt++) {
            const int m = m0 + wm * 64 + mt * 16 + g;
            *(unsigned*)(out + (size_t)m * DMODEL + n) =
                h2u((acc[mt][nt][0] + bx) * osc, (acc[mt][nt][1] + by) * osc);
            *(unsigned*)(out + (size_t)(m + 8) * DMODEL + n) =
                h2u((acc[mt][nt][2] + bx) * osc, (acc[mt][nt][3] + by) * osc);
        }
    }
}

// Final projection: att(half) @ Wc -> fp32 out
__global__ __launch_bounds__(256, 2)
void gemmf_kernel(const __half* __restrict__ A, const __half* __restrict__ W,
                  const float* __restrict__ bias, float* __restrict__ out)
{
    const int m0 = blockIdx.y * 128;
    const int n0 = blockIdx.x * 128;
    float acc[4][4][4];
    gemm_core(A, W, m0, n0, acc);

    const int warp = threadIdx.x >> 5;
    const int lane = threadIdx.x & 31;
    const int g = lane >> 2, th = lane & 3;
    const int wm = warp >> 2, wn = warp & 3;

#pragma unroll
    for (int nt = 0; nt < 4; nt++) {
        const int n = n0 + wn * 32 + nt * 8 + 2 * th;
        const float bx = bias[n], by = bias[n + 1];
#pragma unroll
        for (int mt = 0; mt < 4; mt++) {
            const int m = m0 + wm * 64 + mt * 16 + g;
            *(float2*)(out + (size_t)m * DMODEL + n) =
                make_float2(acc[mt][nt][0] + bx, acc[mt][nt][1] + by);
            *(float2*)(out + (size_t)(m + 8) * DMODEL + n) =
                make_float2(acc[mt][nt][2] + bx, acc[mt][nt][3] + by);
        }
    }
}

// ============================================================================
// Flash attention (half in/out). Block = 128 q rows; kv streamed in 64-row
// tiles with 3-stage cp.async pipeline. 8 warps; warp owns 16 q rows.
// Q fragments hoisted (loop-invariant). V fed via ldmatrix.trans.
// smem: Q 16KB + 3 stages x (K 8KB + V 8KB) = 64KB.
// ============================================================================
#define F_Q_BYTES 0x4000
#define F_STG     0x4000          // K 8KB + V 8KB
#define FA_SMEM   (F_Q_BYTES + 3 * F_STG)   // 65536 B

__device__ __forceinline__ void f_stageKV(uint32_t sK, uint32_t sV,
                                          const __half* __restrict__ kp,
                                          const __half* __restrict__ vp,
                                          size_t base, int kt, int tid)
{
#pragma unroll
    for (int i = 0; i < 2; i++) {
        const int idx = i * 256 + tid;
        const int r = idx >> 3;
        const int c = idx & 7;
        const uint32_t off = (r << 7) + ((c ^ (r & 7)) << 4);
        CP16(sK + off, kp + base + (size_t)(kt + r) * DMODEL + c * 8);
        CP16(sV + off, vp + base + (size_t)(kt + r) * DMODEL + c * 8);
    }
}

__global__ __launch_bounds__(256, 2)
void flash_attn_kernel(const __half* __restrict__ qp,
                       const __half* __restrict__ kp,
                       const __half* __restrict__ vp,
                       __half* __restrict__ att)
{
    extern __shared__ __align__(1024) unsigned char smraw[];
    const uint32_t sQ = cvta_s(smraw);
    const int tid  = threadIdx.x;
    const int warp = tid >> 5;
    const int lane = tid & 31;
    const int g    = lane >> 2;
    const int th   = lane & 3;
    const int qr0  = warp * 16;

    const int s0 = blockIdx.x * 128;
    const int h  = blockIdx.y;
    const int b  = blockIdx.z;
    const size_t base = (size_t)b * SEQ * DMODEL + (size_t)h * DHEAD;

    // stage Q (group 0)
#pragma unroll
    for (int i = 0; i < 4; i++) {
        const int idx = i * 256 + tid;
        const int r = idx >> 3;
        const int c = idx & 7;
        CP16(sQ + (r << 7) + ((c ^ (r & 7)) << 4),
             qp + base + (size_t)(s0 + r) * DMODEL + c * 8);
    }
    CPCOMMIT();
    // stage KV tiles 0, 1
    f_stageKV(sQ + F_Q_BYTES,         sQ + F_Q_BYTES + 0x2000,         kp, vp, base, 0,  tid); CPCOMMIT();
    f_stageKV(sQ + F_Q_BYTES + F_STG, sQ + F_Q_BYTES + F_STG + 0x2000, kp, vp, base, 64, tid); CPCOMMIT();

    // Q fragments (loop-invariant)
    CPWAIT(2);
    __syncthreads();
    unsigned qa[4][4];
#pragma unroll
    for (int kk = 0; kk < 4; kk++)
        ldsm_x4(qa[kk][0], qa[kk][1], qa[kk][2], qa[kk][3],
                lda_nt(sQ, qr0, kk * 2, lane));

    float oacc[8][4];
#pragma unroll
    for (int nt = 0; nt < 8; nt++)
#pragma unroll
        for (int i = 0; i < 4; i++) oacc[nt][i] = 0.f;
    float mrun0 = -INFINITY, mrun1 = -INFINITY;
    float lrun0 = 0.f, lrun1 = 0.f;

    const int NIT = SEQ / 64;   // 32
    for (int it = 0; it < NIT; it++) {
        if (it == NIT - 1) { CPWAIT(0); } else { CPWAIT(1); }
        __syncthreads();
        if (it + 2 < NIT) {
            const uint32_t sn = sQ + F_Q_BYTES + ((it + 2) % 3) * F_STG;
            f_stageKV(sn, sn + 0x2000, kp, vp, base, (it + 2) * 64, tid);
            CPCOMMIT();
        }
        const uint32_t sK = sQ + F_Q_BYTES + (it % 3) * F_STG;
        const uint32_t sV = sK + 0x2000;

        // ---- S = (Q/8) K^T : warp 16 x 64 ----
        float sacc[8][4];
#pragma unroll
        for (int nt = 0; nt < 8; nt++)
#pragma unroll
            for (int i = 0; i < 4; i++) sacc[nt][i] = 0.f;

#pragma unroll
        for (int kk = 0; kk < 4; kk++) {
            unsigned bf[4][4];
#pragma unroll
            for (int np = 0; np < 4; np++)
                ldsm_x4(bf[np][0], bf[np][1], bf[np][2], bf[np][3],
                        lda_nt(sK, np * 16, kk * 2, lane));
#pragma unroll
            for (int nt = 0; nt < 8; nt++) {
                const int np = nt >> 1, sb = nt & 1;
                mma_f16(sacc[nt], qa[kk][0], qa[kk][1], qa[kk][2], qa[kk][3],
                        bf[np][sb], bf[np][sb + 2]);
            }
        }

        // ---- online softmax (rows g, g+8), reduce across th via shfl ----
        float mx0 = -INFINITY, mx1 = -INFINITY;
#pragma unroll
        for (int nt = 0; nt < 8; nt++) {
            mx0 = fmaxf(mx0, fmaxf(sacc[nt][0], sacc[nt][1]));
            mx1 = fmaxf(mx1, fmaxf(sacc[nt][2], sacc[nt][3]));
        }
        mx0 = fmaxf(mx0, __shfl_xor_sync(0xffffffffu, mx0, 1));
        mx0 = fmaxf(mx0, __shfl_xor_sync(0xffffffffu, mx0, 2));
        mx1 = fmaxf(mx1, __shfl_xor_sync(0xffffffffu, mx1, 1));
        mx1 = fmaxf(mx1, __shfl_xor_sync(0xffffffffu, mx1, 2));

        const float mnew0 = fmaxf(mrun0, mx0);
        const float mnew1 = fmaxf(mrun1, mx1);
        const float alpha0 = __expf(mrun0 - mnew0);
        const float alpha1 = __expf(mrun1 - mnew1);
        mrun0 = mnew0; mrun1 = mnew1;

        float ps0 = 0.f, ps1 = 0.f;
#pragma unroll
        for (int nt = 0; nt < 8; nt++) {
            sacc[nt][0] = __expf(sacc[nt][0] - mnew0);
            sacc[nt][1] = __expf(sacc[nt][1] - mnew0);
            sacc[nt][2] = __expf(sacc[nt][2] - mnew1);
            sacc[nt][3] = __expf(sacc[nt][3] - mnew1);
            ps0 += sacc[nt][0] + sacc[nt][1];
            ps1 += sacc[nt][2] + sacc[nt][3];
        }
        ps0 += __shfl_xor_sync(0xffffffffu, ps0, 1);
        ps0 += __shfl_xor_sync(0xffffffffu, ps0, 2);
        ps1 += __shfl_xor_sync(0xffffffffu, ps1, 1);
        ps1 += __shfl_xor_sync(0xffffffffu, ps1, 2);
        lrun0 = lrun0 * alpha0 + ps0;
        lrun1 = lrun1 * alpha1 + ps1;

#pragma unroll
        for (int nt = 0; nt < 8; nt++) {
            oacc[nt][0] *= alpha0; oacc[nt][1] *= alpha0;
            oacc[nt][2] *= alpha1; oacc[nt][3] *= alpha1;
        }

        // ---- O += P @ V : P repacked from S accumulators; V via LDSM.trans --
#pragma unroll
        for (int c = 0; c < 4; c++) {
            const unsigned pa0 = h2u(sacc[2 * c][0],     sacc[2 * c][1]);
            const unsigned pa1 = h2u(sacc[2 * c][2],     sacc[2 * c][3]);
            const unsigned pa2 = h2u(sacc[2 * c + 1][0], sacc[2 * c + 1][1]);
            const unsigned pa3 = h2u(sacc[2 * c + 1][2], sacc[2 * c + 1][3]);
            unsigned vf[4][4];
#pragma unroll
            for (int dp = 0; dp < 4; dp++)
                ldsm_x4t(vf[dp][0], vf[dp][1], vf[dp][2], vf[dp][3],
                         lda_tr(sV, c * 16, dp * 2, lane));
#pragma unroll
            for (int nt = 0; nt < 8; nt++) {
                const int dp = nt >> 1, sb = nt & 1;
                mma_f16(oacc[nt], pa0, pa1, pa2, pa3, vf[dp][sb], vf[dp][sb + 2]);
            }
        }
    }

    // ---- epilogue: half att ----
    const float invl0 = 1.0f / lrun0;
    const float invl1 = 1.0f / lrun1;
    const int row0 = s0 + qr0 + g;
    const int row1 = row0 + 8;
#pragma unroll
    for (int nt = 0; nt < 8; nt++) {
        const int dv = nt * 8 + 2 * th;
        *(unsigned*)(att + base + (size_t)row0 * DMODEL + dv) =
            h2u(oacc[nt][0] * invl0, oacc[nt][1] * invl0);
        *(unsigned*)(att + base + (size_t)row1 * DMODEL + dv) =
            h2u(oacc[nt][2] * invl1, oacc[nt][3] * invl1);
    }
}

// ---------------- host launcher ---------------------------------------------
extern "C" void kernel_launch(void* const* d_in, const int* in_sizes, int n_in,
                              void* d_out, int out_size)
{
    const float* q    = (const float*)d_in[0];
    const float* k    = (const float*)d_in[1];
    const float* v    = (const float*)d_in[2];
    const float* Wq_w = (const float*)d_in[3];
    const float* Wq_b = (const float*)d_in[4];
    const float* Wc_w = (const float*)d_in[5];
    const float* Wc_b = (const float*)d_in[6];
    float* out = (float*)d_out;

    __half *qh, *kh, *vh, *Wqh, *Wch, *qp, *kp, *vp, *attp;
    cudaGetSymbolAddress((void**)&qh,   g_qh);
    cudaGetSymbolAddress((void**)&kh,   g_kh);
    cudaGetSymbolAddress((void**)&vh,   g_vh);
    cudaGetSymbolAddress((void**)&Wqh,  g_Wqh);
    cudaGetSymbolAddress((void**)&Wch,  g_Wch);
    cudaGetSymbolAddress((void**)&qp,   g_qp);
    cudaGetSymbolAddress((void**)&kp,   g_kp);
    cudaGetSymbolAddress((void**)&vp,   g_vp);
    cudaGetSymbolAddress((void**)&attp, g_att);

    cudaFuncSetAttribute(proj3_kernel,
                         cudaFuncAttributeMaxDynamicSharedMemorySize, GEMM_SMEM);
    cudaFuncSetAttribute(gemmf_kernel,
                         cudaFuncAttributeMaxDynamicSharedMemorySize, GEMM_SMEM);
    cudaFuncSetAttribute(flash_attn_kernel,
                         cudaFuncAttributeMaxDynamicSharedMemorySize, FA_SMEM);

    // 1) fp32 -> fp16 conversions
    dim3 cgrid(MTOT * DMODEL / 2048, 1, 3);    // (1024,1,3)
    cvt3_kernel<<<cgrid, 256>>>(q, k, v, qh, kh, vh);
    dim3 wgrid(DMODEL * DMODEL / 2048, 1, 2);  // (128,1,2)
    cvtW_kernel<<<wgrid, 256>>>(Wq_w, Wc_w, Wqh, Wch);

    // 2) three input projections (all use Wq; q output scaled by 1/8)
    dim3 pgrid(DMODEL / 128, MTOT / 128, 3);   // (4, 32, 3)
    proj3_kernel<<<pgrid, 256, GEMM_SMEM>>>(qh, kh, vh, Wqh, Wq_b, qp, kp, vp);

    // 3) flash attention
    dim3 fgrid(SEQ / 128, NHEADS, BATCH);      // (16, 8, 2)
    flash_attn_kernel<<<fgrid, 256, FA_SMEM>>>(qp, kp, vp, attp);

    // 4) output projection (half -> fp32)
    dim3 ogrid(DMODEL / 128, MTOT / 128);      // (4, 32)
    gemmf_kernel<<<ogrid, 256, GEMM_SMEM>>>(attp, Wch, Wc_b, out);
}

// round 7
// speedup vs baseline: 8.8928x; 1.0202x over previous
#include <cuda_runtime.h>
#include <cuda_fp16.h>
#include <cstdint>
#include <math.h>

// Problem constants
#define BATCH   2
#define SEQ     2048
#define DMODEL  512
#define NHEADS  8
#define DHEAD   64
#define MTOT    (BATCH * SEQ)

// ---------------- scratch (static device arrays; no allocation) -------------
__device__ __half g_qh [MTOT * DMODEL];     // half copies of inputs
__device__ __half g_kh [MTOT * DMODEL];
__device__ __half g_vh [MTOT * DMODEL];
__device__ __half g_Wqh[DMODEL * DMODEL];
__device__ __half g_Wch[DMODEL * DMODEL];
__device__ __half g_qp [MTOT * DMODEL];     // q pre-scaled by 0.125*log2(e)
__device__ __half g_kp [MTOT * DMODEL];
__device__ __half g_vp [MTOT * DMODEL];
__device__ __half g_att[MTOT * DMODEL];     // attention output

#define ONES_H2 0x3C003C00u    // half2(1.0, 1.0)

// ---------------- helpers ----------------------------------------------------
__device__ __forceinline__ unsigned h2u(float lo, float hi) {
    __half2 h = __floats2half2_rn(lo, hi);
    return *(unsigned*)&h;
}

__device__ __forceinline__ void mma_f16(float c[4],
                                        unsigned a0, unsigned a1,
                                        unsigned a2, unsigned a3,
                                        unsigned b0, unsigned b1) {
    asm volatile(
        "mma.sync.aligned.m16n8k16.row.col.f32.f16.f16.f32 "
        "{%0,%1,%2,%3}, {%4,%5,%6,%7}, {%8,%9}, {%0,%1,%2,%3};"
        : "+f"(c[0]), "+f"(c[1]), "+f"(c[2]), "+f"(c[3])
        : "r"(a0), "r"(a1), "r"(a2), "r"(a3), "r"(b0), "r"(b1));
}

__device__ __forceinline__ uint32_t cvta_s(const void* p) {
    return (uint32_t)__cvta_generic_to_shared(p);
}

#define CP16(dst, src) \
    asm volatile("cp.async.cg.shared.global [%0], [%1], 16;" :: "r"(dst), "l"(src))
#define CPCOMMIT() asm volatile("cp.async.commit_group;")
#define CPWAIT(n)  asm volatile("cp.async.wait_group %0;" :: "n"(n))

__device__ __forceinline__ void ldsm_x4(unsigned& r0, unsigned& r1,
                                        unsigned& r2, unsigned& r3, uint32_t addr) {
    asm volatile("ldmatrix.sync.aligned.m8n8.x4.shared.b16 {%0,%1,%2,%3}, [%4];"
                 : "=r"(r0), "=r"(r1), "=r"(r2), "=r"(r3) : "r"(addr));
}
__device__ __forceinline__ void ldsm_x4t(unsigned& r0, unsigned& r1,
                                         unsigned& r2, unsigned& r3, uint32_t addr) {
    asm volatile("ldmatrix.sync.aligned.m8n8.x4.trans.shared.b16 {%0,%1,%2,%3}, [%4];"
                 : "=r"(r0), "=r"(r1), "=r"(r2), "=r"(r3) : "r"(addr));
}

// All smem tiles: 128B rows (64 halves), swizzle chunk c -> c ^ (row & 7).
__device__ __forceinline__ uint32_t lda_nt(uint32_t base, int R, int c0, int lane) {
    const int r = R + (lane & 7) + (lane & 8);
    const int c = c0 + (lane >> 4);
    return base + (r << 7) + ((c ^ (r & 7)) << 4);
}
__device__ __forceinline__ uint32_t lda_tr(uint32_t base, int KB, int c0, int lane) {
    const int r = KB + ((lane >> 1) & 8) + (lane & 7);
    const int c = c0 + ((lane >> 3) & 1);
    return base + (r << 7) + ((c ^ (r & 7)) << 4);
}

// ---------------- conversion kernels -----------------------------------------
__global__ __launch_bounds__(256)
void cvt3_kernel(const float* __restrict__ q, const float* __restrict__ k,
                 const float* __restrict__ v,
                 __half* __restrict__ qh, __half* __restrict__ kh,
                 __half* __restrict__ vh)
{
    const float* s; __half* d;
    if (blockIdx.z == 0)      { s = q; d = qh; }
    else if (blockIdx.z == 1) { s = k; d = kh; }
    else                      { s = v; d = vh; }
    const size_t i = ((size_t)blockIdx.x * 256 + threadIdx.x) * 8;
    float4 a = *(const float4*)(s + i);
    float4 b = *(const float4*)(s + i + 4);
    uint4 o;
    o.x = h2u(a.x, a.y); o.y = h2u(a.z, a.w);
    o.z = h2u(b.x, b.y); o.w = h2u(b.z, b.w);
    *(uint4*)(d + i) = o;
}

__global__ __launch_bounds__(256)
void cvtW_kernel(const float* __restrict__ Wq, const float* __restrict__ Wc,
                 __half* __restrict__ Wqh, __half* __restrict__ Wch)
{
    const float* s = blockIdx.z == 0 ? Wq : Wc;
    __half* d      = blockIdx.z == 0 ? Wqh : Wch;
    const size_t i = ((size_t)blockIdx.x * 256 + threadIdx.x) * 8;
    float4 a = *(const float4*)(s + i);
    float4 b = *(const float4*)(s + i + 4);
    uint4 o;
    o.x = h2u(a.x, a.y); o.y = h2u(a.z, a.w);
    o.z = h2u(b.x, b.y); o.w = h2u(b.z, b.w);
    *(uint4*)(d + i) = o;
}

// ============================================================================
// half GEMM core (unchanged from round 6)
// ============================================================================
#define G_STG 0x8000           // 32KB per stage (A+W)
#define GEMM_SMEM (3 * G_STG)  // 98304 B

__device__ __forceinline__ void g_stage(uint32_t sA, uint32_t sW,
                                        const __half* __restrict__ A,
                                        const __half* __restrict__ W,
                                        int m0, int n0, int kt, int tid)
{
#pragma unroll
    for (int i = 0; i < 4; i++) {
        const int idx = i * 256 + tid;
        const int r = idx >> 3;
        const int c = idx & 7;
        const uint32_t off = (r << 7) + ((c ^ (r & 7)) << 4);
        CP16(sA + off, A + (size_t)(m0 + r) * DMODEL + kt + c * 8);
        CP16(sW + off, W + (size_t)(n0 + r) * DMODEL + kt + c * 8);
    }
}

__device__ __forceinline__ void gemm_core(const __half* __restrict__ A,
                                          const __half* __restrict__ W,
                                          int m0, int n0,
                                          float acc[4][4][4])
{
    extern __shared__ __align__(1024) unsigned char smraw[];
    const uint32_t sbase = cvta_s(smraw);
    const int tid  = threadIdx.x;
    const int warp = tid >> 5;
    const int lane = tid & 31;
    const int wm   = warp >> 2;
    const int wn   = warp & 3;

#pragma unroll
    for (int mt = 0; mt < 4; mt++)
#pragma unroll
        for (int nt = 0; nt < 4; nt++)
#pragma unroll
            for (int i = 0; i < 4; i++) acc[mt][nt][i] = 0.f;

    g_stage(sbase,         sbase + 0x4000,         A, W, m0, n0, 0,  tid); CPCOMMIT();
    g_stage(sbase + G_STG, sbase + G_STG + 0x4000, A, W, m0, n0, 64, tid); CPCOMMIT();

    const int NIT = DMODEL / 64;   // 8
    for (int it = 0; it < NIT; it++) {
        if (it == NIT - 1) { CPWAIT(0); } else { CPWAIT(1); }
        __syncthreads();
        if (it + 2 < NIT) {
            const uint32_t sn = sbase + ((it + 2) % 3) * G_STG;
            g_stage(sn, sn + 0x4000, A, W, m0, n0, (it + 2) * 64, tid);
            CPCOMMIT();
        }
        const uint32_t sA = sbase + (it % 3) * G_STG;
        const uint32_t sW = sA + 0x4000;

#pragma unroll
        for (int kk = 0; kk < 4; kk++) {
            unsigned a[4][4];
#pragma unroll
            for (int mt = 0; mt < 4; mt++)
                ldsm_x4(a[mt][0], a[mt][1], a[mt][2], a[mt][3],
                        lda_nt(sA, wm * 64 + mt * 16, kk * 2, lane));
            unsigned bf[2][4];
#pragma unroll
            for (int np = 0; np < 2; np++)
                ldsm_x4(bf[np][0], bf[np][1], bf[np][2], bf[np][3],
                        lda_nt(sW, wn * 32 + np * 16, kk * 2, lane));
#pragma unroll
            for (int nt = 0; nt < 4; nt++) {
                const int np = nt >> 1, sb = nt & 1;
#pragma unroll
                for (int mt = 0; mt < 4; mt++)
                    mma_f16(acc[mt][nt], a[mt][0], a[mt][1], a[mt][2], a[mt][3],
                            bf[np][sb], bf[np][sb + 2]);
            }
        }
    }
}

// Projections: q output pre-scaled by 0.125*log2(e) for exp2-domain softmax.
__global__ __launch_bounds__(256, 2)
void proj3_kernel(const __half* __restrict__ qh, const __half* __restrict__ kh,
                  const __half* __restrict__ vh, const __half* __restrict__ W,
                  const float* __restrict__ bias,
                  __half* __restrict__ qp, __half* __restrict__ kp,
                  __half* __restrict__ vp)
{
    const __half* A; __half* out; float osc;
    if (blockIdx.z == 0)      { A = qh; out = qp; osc = 0.125f * 1.44269504089f; }
    else if (blockIdx.z == 1) { A = kh; out = kp; osc = 1.0f;   }
    else                      { A = vh; out = vp; osc = 1.0f;   }

    const int m0 = blockIdx.y * 128;
    const int n0 = blockIdx.x * 128;
    float acc[4][4][4];
    gemm_core(A, W, m0, n0, acc);

    const int warp = threadIdx.x >> 5;
    const int lane = threadIdx.x & 31;
    const int g = lane >> 2, th = lane & 3;
    const int wm = warp >> 2, wn = warp & 3;

#pragma unroll
    for (int nt = 0; nt < 4; nt++) {
        const int n = n0 + wn * 32 + nt * 8 + 2 * th;
        const float bx = bias[n], by = bias[n + 1];
#pragma unroll
        for (int mt = 0; mt < 4; mt++) {
            const int m = m0 + wm * 64 + mt * 16 + g;
            *(unsigned*)(out + (size_t)m * DMODEL + n) =
                h2u((acc[mt][nt][0] + bx) * osc, (acc[mt][nt][1] + by) * osc);
            *(unsigned*)(out + (size_t)(m + 8) * DMODEL + n) =
                h2u((acc[mt][nt][2] + bx) * osc, (acc[mt][nt][3] + by) * osc);
        }
    }
}

// Final projection: att(half) @ Wc -> fp32 out
__global__ __launch_bounds__(256, 2)
void gemmf_kernel(const __half* __restrict__ A, const __half* __restrict__ W,
                  const float* __restrict__ bias, float* __restrict__ out)
{
    const int m0 = blockIdx.y * 128;
    const int n0 = blockIdx.x * 128;
    float acc[4][4][4];
    gemm_core(A, W, m0, n0, acc);

    const int warp = threadIdx.x >> 5;
    const int lane = threadIdx.x & 31;
    const int g = lane >> 2, th = lane & 3;
    const int wm = warp >> 2, wn = warp & 3;

#pragma unroll
    for (int nt = 0; nt < 4; nt++) {
        const int n = n0 + wn * 32 + nt * 8 + 2 * th;
        const float bx = bias[n], by = bias[n + 1];
#pragma unroll
        for (int mt = 0; mt < 4; mt++) {
            const int m = m0 + wm * 64 + mt * 16 + g;
            *(float2*)(out + (size_t)m * DMODEL + n) =
                make_float2(acc[mt][nt][0] + bx, acc[mt][nt][1] + by);
            *(float2*)(out + (size_t)(m + 8) * DMODEL + n) =
                make_float2(acc[mt][nt][2] + bx, acc[mt][nt][3] + by);
        }
    }
}

// ============================================================================
// Flash attention (half in/out), exp2-domain softmax, row-sums via ones-mma.
// ============================================================================
#define F_Q_BYTES 0x4000
#define F_STG     0x4000          // K 8KB + V 8KB
#define FA_SMEM   (F_Q_BYTES + 3 * F_STG)   // 65536 B

__device__ __forceinline__ void f_stageKV(uint32_t sK, uint32_t sV,
                                          const __half* __restrict__ kp,
                                          const __half* __restrict__ vp,
                                          size_t base, int kt, int tid)
{
#pragma unroll
    for (int i = 0; i < 2; i++) {
        const int idx = i * 256 + tid;
        const int r = idx >> 3;
        const int c = idx & 7;
        const uint32_t off = (r << 7) + ((c ^ (r & 7)) << 4);
        CP16(sK + off, kp + base + (size_t)(kt + r) * DMODEL + c * 8);
        CP16(sV + off, vp + base + (size_t)(kt + r) * DMODEL + c * 8);
    }
}

__global__ __launch_bounds__(256, 2)
void flash_attn_kernel(const __half* __restrict__ qp,
                       const __half* __restrict__ kp,
                       const __half* __restrict__ vp,
                       __half* __restrict__ att)
{
    extern __shared__ __align__(1024) unsigned char smraw[];
    const uint32_t sQ = cvta_s(smraw);
    const int tid  = threadIdx.x;
    const int warp = tid >> 5;
    const int lane = tid & 31;
    const int g    = lane >> 2;
    const int th   = lane & 3;
    const int qr0  = warp * 16;

    const int s0 = blockIdx.x * 128;
    const int h  = blockIdx.y;
    const int b  = blockIdx.z;
    const size_t base = (size_t)b * SEQ * DMODEL + (size_t)h * DHEAD;

    // stage Q (group 0)
#pragma unroll
    for (int i = 0; i < 4; i++) {
        const int idx = i * 256 + tid;
        const int r = idx >> 3;
        const int c = idx & 7;
        CP16(sQ + (r << 7) + ((c ^ (r & 7)) << 4),
             qp + base + (size_t)(s0 + r) * DMODEL + c * 8);
    }
    CPCOMMIT();
    f_stageKV(sQ + F_Q_BYTES,         sQ + F_Q_BYTES + 0x2000,         kp, vp, base, 0,  tid); CPCOMMIT();
    f_stageKV(sQ + F_Q_BYTES + F_STG, sQ + F_Q_BYTES + F_STG + 0x2000, kp, vp, base, 64, tid); CPCOMMIT();

    // Q fragments (loop-invariant)
    CPWAIT(2);
    __syncthreads();
    unsigned qa[4][4];
#pragma unroll
    for (int kk = 0; kk < 4; kk++)
        ldsm_x4(qa[kk][0], qa[kk][1], qa[kk][2], qa[kk][3],
                lda_nt(sQ, qr0, kk * 2, lane));

    float oacc[8][4];
#pragma unroll
    for (int nt = 0; nt < 8; nt++)
#pragma unroll
        for (int i = 0; i < 4; i++) oacc[nt][i] = 0.f;
    float lacc[4] = {0.f, 0.f, 0.f, 0.f};   // row-sum accumulator (ones-mma)
    float mrun0 = -INFINITY, mrun1 = -INFINITY;

    const int NIT = SEQ / 64;   // 32
    for (int it = 0; it < NIT; it++) {
        if (it == NIT - 1) { CPWAIT(0); } else { CPWAIT(1); }
        __syncthreads();
        if (it + 2 < NIT) {
            const uint32_t sn = sQ + F_Q_BYTES + ((it + 2) % 3) * F_STG;
            f_stageKV(sn, sn + 0x2000, kp, vp, base, (it + 2) * 64, tid);
            CPCOMMIT();
        }
        const uint32_t sK = sQ + F_Q_BYTES + (it % 3) * F_STG;
        const uint32_t sV = sK + 0x2000;

        // ---- S (log2-domain) = Q' K^T : warp 16 x 64 ----
        float sacc[8][4];
#pragma unroll
        for (int nt = 0; nt < 8; nt++)
#pragma unroll
            for (int i = 0; i < 4; i++) sacc[nt][i] = 0.f;

#pragma unroll
        for (int kk = 0; kk < 4; kk++) {
            unsigned bf[4][4];
#pragma unroll
            for (int np = 0; np < 4; np++)
                ldsm_x4(bf[np][0], bf[np][1], bf[np][2], bf[np][3],
                        lda_nt(sK, np * 16, kk * 2, lane));
#pragma unroll
            for (int nt = 0; nt < 8; nt++) {
                const int np = nt >> 1, sb = nt & 1;
                mma_f16(sacc[nt], qa[kk][0], qa[kk][1], qa[kk][2], qa[kk][3],
                        bf[np][sb], bf[np][sb + 2]);
            }
        }

        // ---- online softmax in exp2 domain; rows g, g+8 ----
        float mx0 = -INFINITY, mx1 = -INFINITY;
#pragma unroll
        for (int nt = 0; nt < 8; nt++) {
            mx0 = fmaxf(mx0, fmaxf(sacc[nt][0], sacc[nt][1]));
            mx1 = fmaxf(mx1, fmaxf(sacc[nt][2], sacc[nt][3]));
        }
        mx0 = fmaxf(mx0, __shfl_xor_sync(0xffffffffu, mx0, 1));
        mx0 = fmaxf(mx0, __shfl_xor_sync(0xffffffffu, mx0, 2));
        mx1 = fmaxf(mx1, __shfl_xor_sync(0xffffffffu, mx1, 1));
        mx1 = fmaxf(mx1, __shfl_xor_sync(0xffffffffu, mx1, 2));

        const float mnew0 = fmaxf(mrun0, mx0);
        const float mnew1 = fmaxf(mrun1, mx1);
        const float alpha0 = exp2f(mrun0 - mnew0);
        const float alpha1 = exp2f(mrun1 - mnew1);
        mrun0 = mnew0; mrun1 = mnew1;

#pragma unroll
        for (int nt = 0; nt < 8; nt++) {
            sacc[nt][0] = exp2f(sacc[nt][0] - mnew0);
            sacc[nt][1] = exp2f(sacc[nt][1] - mnew0);
            sacc[nt][2] = exp2f(sacc[nt][2] - mnew1);
            sacc[nt][3] = exp2f(sacc[nt][3] - mnew1);
        }

#pragma unroll
        for (int nt = 0; nt < 8; nt++) {
            oacc[nt][0] *= alpha0; oacc[nt][1] *= alpha0;
            oacc[nt][2] *= alpha1; oacc[nt][3] *= alpha1;
        }
        lacc[0] *= alpha0; lacc[1] *= alpha0;
        lacc[2] *= alpha1; lacc[3] *= alpha1;

        // ---- O += P @ V ; l += P @ 1 : P repacked from S accumulators ----
#pragma unroll
        for (int c = 0; c < 4; c++) {
            const unsigned pa0 = h2u(sacc[2 * c][0],     sacc[2 * c][1]);
            const unsigned pa1 = h2u(sacc[2 * c][2],     sacc[2 * c][3]);
            const unsigned pa2 = h2u(sacc[2 * c + 1][0], sacc[2 * c + 1][1]);
            const unsigned pa3 = h2u(sacc[2 * c + 1][2], sacc[2 * c + 1][3]);
            unsigned vf[4][4];
#pragma unroll
            for (int dp = 0; dp < 4; dp++)
                ldsm_x4t(vf[dp][0], vf[dp][1], vf[dp][2], vf[dp][3],
                         lda_tr(sV, c * 16, dp * 2, lane));
#pragma unroll
            for (int nt = 0; nt < 8; nt++) {
                const int dp = nt >> 1, sb = nt & 1;
                mma_f16(oacc[nt], pa0, pa1, pa2, pa3, vf[dp][sb], vf[dp][sb + 2]);
            }
            // row-sum: B = all-ones fragment (layout-independent)
            mma_f16(lacc, pa0, pa1, pa2, pa3, ONES_H2, ONES_H2);
        }
    }

    // ---- epilogue: half att ----
    const float invl0 = 1.0f / lacc[0];
    const float invl1 = 1.0f / lacc[2];
    const int row0 = s0 + qr0 + g;
    const int row1 = row0 + 8;
#pragma unroll
    for (int nt = 0; nt < 8; nt++) {
        const int dv = nt * 8 + 2 * th;
        *(unsigned*)(att + base + (size_t)row0 * DMODEL + dv) =
            h2u(oacc[nt][0] * invl0, oacc[nt][1] * invl0);
        *(unsigned*)(att + base + (size_t)row1 * DMODEL + dv) =
            h2u(oacc[nt][2] * invl1, oacc[nt][3] * invl1);
    }
}

// ---------------- host launcher ---------------------------------------------
extern "C" void kernel_launch(void* const* d_in, const int* in_sizes, int n_in,
                              void* d_out, int out_size)
{
    const float* q    = (const float*)d_in[0];
    const float* k    = (const float*)d_in[1];
    const float* v    = (const float*)d_in[2];
    const float* Wq_w = (const float*)d_in[3];
    const float* Wq_b = (const float*)d_in[4];
    const float* Wc_w = (const float*)d_in[5];
    const float* Wc_b = (const float*)d_in[6];
    float* out = (float*)d_out;

    __half *qh, *kh, *vh, *Wqh, *Wch, *qp, *kp, *vp, *attp;
    cudaGetSymbolAddress((void**)&qh,   g_qh);
    cudaGetSymbolAddress((void**)&kh,   g_kh);
    cudaGetSymbolAddress((void**)&vh,   g_vh);
    cudaGetSymbolAddress((void**)&Wqh,  g_Wqh);
    cudaGetSymbolAddress((void**)&Wch,  g_Wch);
    cudaGetSymbolAddress((void**)&qp,   g_qp);
    cudaGetSymbolAddress((void**)&kp,   g_kp);
    cudaGetSymbolAddress((void**)&vp,   g_vp);
    cudaGetSymbolAddress((void**)&attp, g_att);

    cudaFuncSetAttribute(proj3_kernel,
                         cudaFuncAttributeMaxDynamicSharedMemorySize, GEMM_SMEM);
    cudaFuncSetAttribute(gemmf_kernel,
                         cudaFuncAttributeMaxDynamicSharedMemorySize, GEMM_SMEM);
    cudaFuncSetAttribute(flash_attn_kernel,
                         cudaFuncAttributeMaxDynamicSharedMemorySize, FA_SMEM);

    // 1) fp32 -> fp16 conversions
    dim3 cgrid(MTOT * DMODEL / 2048, 1, 3);    // (1024,1,3)
    cvt3_kernel<<<cgrid, 256>>>(q, k, v, qh, kh, vh);
    dim3 wgrid(DMODEL * DMODEL / 2048, 1, 2);  // (128,1,2)
    cvtW_kernel<<<wgrid, 256>>>(Wq_w, Wc_w, Wqh, Wch);

    // 2) three input projections (all use Wq; q scaled into exp2 domain)
    dim3 pgrid(DMODEL / 128, MTOT / 128, 3);   // (4, 32, 3)
    proj3_kernel<<<pgrid, 256, GEMM_SMEM>>>(qh, kh, vh, Wqh, Wq_b, qp, kp, vp);

    // 3) flash attention
    dim3 fgrid(SEQ / 128, NHEADS, BATCH);      // (16, 8, 2)
    flash_attn_kernel<<<fgrid, 256, FA_SMEM>>>(qp, kp, vp, attp);

    // 4) output projection (half -> fp32)
    dim3 ogrid(DMODEL / 128, MTOT / 128);      // (4, 32)
    gemmf_kernel<<<ogrid, 256, GEMM_SMEM>>>(attp, Wch, Wc_b, out);
}